// round 1
// baseline (speedup 1.0000x reference)
#include <cuda_runtime.h>
#include <math.h>

#define B_ 4
#define L_ 1024
#define H_ 1024
#define NH_ 16
#define M_ 64
#define E_ 24
#define R_ 512
#define EMB_ 768
#define NCLS_ 97
#define KB_ 12            // EMB / 64
#define BR_ 2048          // B*R
#define WROWS_ 49152      // EMB*64
#define WLD_ 128          // padded N stride for Wbc

// ---------------- scratch (static device globals; no allocation) -------------
__device__ int   g_cnt[B_*E_];
__device__ int   g_mlist[B_*E_*M_];
__device__ float g_entemb[B_*E_*H_];
__device__ float g_entattn[B_*E_*NH_*L_];
__device__ float g_ht[B_*R_*L_];
__device__ float g_rel[B_*R_*H_];
__device__ float g_he[BR_*EMB_];
__device__ float g_te[BR_*EMB_];
__device__ float g_Hh[B_*E_*EMB_];
__device__ float g_Ht[B_*E_*EMB_];
__device__ float g_Wbc[WROWS_*WLD_];
__device__ float g_part[KB_*BR_*NCLS_];
__device__ float g_bbc[NCLS_];

// ---------------- K0: mention lists per (b,e) --------------------------------
__global__ void k_prep(const int* __restrict__ labels) {
    int t = threadIdx.x;
    if (t < B_*E_) {
        int b = t / E_, e = t % E_;
        int c = 0;
        for (int m = 0; m < M_; m++)
            if (labels[b*M_ + m] == e) g_mlist[t*M_ + c++] = m;
        g_cnt[t] = c;
    }
}

// ---------------- bbc = bb @ Wc + bc ----------------------------------------
__global__ void k_bbc(const float* __restrict__ bb, const float* __restrict__ Wc,
                      const float* __restrict__ bc) {
    int n = threadIdx.x;
    if (n < NCLS_) {
        float a = bc[n];
        for (int d = 0; d < EMB_; d++) a += bb[d] * Wc[d*NCLS_ + n];
        g_bbc[n] = a;
    }
}

// ---------------- K1: entity logsumexp pooling -------------------------------
__global__ void k_entemb(const float* __restrict__ ent) {
    int be = blockIdx.x;
    int b = be / E_;
    __shared__ int lst[M_];
    __shared__ int scnt;
    if (threadIdx.x == 0) scnt = g_cnt[be];
    __syncthreads();
    int cnt = scnt;
    if (threadIdx.x < cnt) lst[threadIdx.x] = g_mlist[be*M_ + threadIdx.x];
    __syncthreads();
    for (int h = threadIdx.x; h < H_; h += blockDim.x) {
        float o = 0.f;
        if (cnt > 0) {
            float mx = -3.4e38f;
            for (int c = 0; c < cnt; c++)
                mx = fmaxf(mx, ent[(b*M_ + lst[c])*H_ + h]);
            float s = 0.f;
            for (int c = 0; c < cnt; c++)
                s += expf(ent[(b*M_ + lst[c])*H_ + h] - mx);
            o = mx + logf(s);
        }
        g_entemb[be*H_ + h] = o;
    }
}

// ---------------- K2: entity->seq attention (mean over mentions) -------------
__global__ void k_entattn(const float* __restrict__ attn) {
    int be = blockIdx.x, nh = blockIdx.y;
    int b = be / E_;
    __shared__ int lst[M_];
    __shared__ int scnt;
    if (threadIdx.x == 0) scnt = g_cnt[be];
    __syncthreads();
    int cnt = scnt;
    if (threadIdx.x < cnt) lst[threadIdx.x] = g_mlist[be*M_ + threadIdx.x];
    __syncthreads();
    float inv = 1.f / (float)(cnt > 1 ? cnt : 1);
    const float* base = attn + (b*NH_ + nh)*M_*L_;
    float* outp = g_entattn + (be*NH_ + nh)*L_;
    for (int l = threadIdx.x; l < L_; l += blockDim.x) {
        float a = 0.f;
        for (int c = 0; c < cnt; c++) a += base[lst[c]*L_ + l];
        outp[l] = a * inv;
    }
}

// ---------------- K3: pair attention product + normalize ---------------------
__global__ void k_ht(const int* __restrict__ hts) {
    int br = blockIdx.x;
    int b = br >> 9;
    int h = hts[br*2 + 0], t = hts[br*2 + 1];
    const float* ph = g_entattn + (b*E_ + h)*NH_*L_;
    const float* pt = g_entattn + (b*E_ + t)*NH_*L_;
    float v[4];
    float lsum = 0.f;
    #pragma unroll
    for (int q = 0; q < 4; q++) {
        int l = threadIdx.x + q*256;
        float s = 0.f;
        #pragma unroll
        for (int nh = 0; nh < NH_; nh++)
            s += ph[nh*L_ + l] * pt[nh*L_ + l];
        v[q] = s * (1.f/NH_);
        lsum += v[q];
    }
    __shared__ float red[256];
    red[threadIdx.x] = lsum;
    __syncthreads();
    for (int s = 128; s > 0; s >>= 1) {
        if (threadIdx.x < s) red[threadIdx.x] += red[threadIdx.x + s];
        __syncthreads();
    }
    float inv = 1.f / (red[0] + 1e-5f);
    #pragma unroll
    for (int q = 0; q < 4; q++) {
        int l = threadIdx.x + q*256;
        g_ht[br*L_ + l] = v[q] * inv;
    }
}

// ---------------- K4: rel = ht @ seq (per batch GEMM 512x1024x1024) ----------
__global__ void k_rel(const float* __restrict__ seq) {
    const int b = blockIdx.z;
    const float* A = g_ht + b*R_*L_;
    const float* Bm = seq + b*L_*H_;
    float* C = g_rel + b*R_*H_;
    const int row0 = blockIdx.y*128, col0 = blockIdx.x*128;
    __shared__ float As[8][128];
    __shared__ float Bs[8][128];
    float acc[8][8];
    #pragma unroll
    for (int i = 0; i < 8; i++)
        #pragma unroll
        for (int j = 0; j < 8; j++) acc[i][j] = 0.f;
    const int tid = threadIdx.x;
    const int tx = tid & 15, ty = tid >> 4;
    const int am = tid >> 1, ak = (tid & 1)*4;
    const int bk = tid >> 5, bn = (tid & 31)*4;
    for (int kk = 0; kk < L_; kk += 8) {
        float4 av = *(const float4*)&A[(row0+am)*L_ + kk + ak];
        float4 bv = *(const float4*)&Bm[(kk+bk)*H_ + col0 + bn];
        __syncthreads();
        As[ak+0][am] = av.x; As[ak+1][am] = av.y;
        As[ak+2][am] = av.z; As[ak+3][am] = av.w;
        *(float4*)&Bs[bk][bn] = bv;
        __syncthreads();
        #pragma unroll
        for (int k = 0; k < 8; k++) {
            float4 a0 = *(const float4*)&As[k][ty*8];
            float4 a1 = *(const float4*)&As[k][ty*8+4];
            float4 b0 = *(const float4*)&Bs[k][tx*8];
            float4 b1 = *(const float4*)&Bs[k][tx*8+4];
            float ar[8] = {a0.x,a0.y,a0.z,a0.w,a1.x,a1.y,a1.z,a1.w};
            float br[8] = {b0.x,b0.y,b0.z,b0.w,b1.x,b1.y,b1.z,b1.w};
            #pragma unroll
            for (int i = 0; i < 8; i++)
                #pragma unroll
                for (int j = 0; j < 8; j++)
                    acc[i][j] += ar[i]*br[j];
        }
    }
    #pragma unroll
    for (int i = 0; i < 8; i++) {
        int m = row0 + ty*8 + i;
        #pragma unroll
        for (int j = 0; j < 8; j += 4) {
            float4 v = make_float4(acc[i][j],acc[i][j+1],acc[i][j+2],acc[i][j+3]);
            *(float4*)&C[m*H_ + col0 + tx*8 + j] = v;
        }
    }
}

// ---------------- K5a: Hh/Ht = ent_emb @ W*_top (96x1024x768 x2) -------------
__global__ void k_hx(const float* __restrict__ Wh, const float* __restrict__ Wt) {
    const int z = blockIdx.z;
    const float* W = z ? Wt : Wh;
    float* Cout = z ? g_Ht : g_Hh;
    const int row0 = blockIdx.y*32, col0 = blockIdx.x*128;
    __shared__ float As[16][32];
    __shared__ float Bs[16][128];
    float acc[2][8];
    #pragma unroll
    for (int i = 0; i < 2; i++)
        #pragma unroll
        for (int j = 0; j < 8; j++) acc[i][j] = 0.f;
    const int tid = threadIdx.x;
    const int tx = tid & 15, ty = tid >> 4;
    for (int kk = 0; kk < H_; kk += 16) {
        __syncthreads();
        if (tid < 128) {
            int m = tid >> 2, k4 = (tid & 3)*4;
            float4 av = *(const float4*)&g_entemb[(row0+m)*H_ + kk + k4];
            As[k4+0][m] = av.x; As[k4+1][m] = av.y;
            As[k4+2][m] = av.z; As[k4+3][m] = av.w;
        }
        #pragma unroll
        for (int q = 0; q < 2; q++) {
            int idx = q*256 + tid;
            int k = idx >> 5, n4 = (idx & 31)*4;
            *(float4*)&Bs[k][n4] = *(const float4*)&W[(kk+k)*EMB_ + col0 + n4];
        }
        __syncthreads();
        #pragma unroll
        for (int k = 0; k < 16; k++) {
            float a0 = As[k][ty*2], a1 = As[k][ty*2+1];
            float4 b0 = *(const float4*)&Bs[k][tx*8];
            float4 b1 = *(const float4*)&Bs[k][tx*8+4];
            float br[8] = {b0.x,b0.y,b0.z,b0.w,b1.x,b1.y,b1.z,b1.w};
            #pragma unroll
            for (int j = 0; j < 8; j++) {
                acc[0][j] += a0*br[j];
                acc[1][j] += a1*br[j];
            }
        }
    }
    #pragma unroll
    for (int i = 0; i < 2; i++) {
        int m = row0 + ty*2 + i;
        #pragma unroll
        for (int j = 0; j < 8; j += 4) {
            float4 v = make_float4(acc[i][j],acc[i][j+1],acc[i][j+2],acc[i][j+3]);
            *(float4*)&Cout[m*EMB_ + col0 + tx*8 + j] = v;
        }
    }
}

// ---------------- K5b: he/te = tanh(rel @ W*_bot + Hx + b) -------------------
// GEMM M=2048, K=1024, N=1536 (cols <768 -> he/Wh, >=768 -> te/Wt)
__global__ void k_hete(const float* __restrict__ Wh, const float* __restrict__ Wt,
                       const float* __restrict__ bh, const float* __restrict__ bt,
                       const int* __restrict__ hts) {
    const int col0 = blockIdx.x*128, row0 = blockIdx.y*128;
    const bool head = (col0 < EMB_);
    const float* W = head ? Wh : Wt;
    const int nb = head ? col0 : col0 - EMB_;
    __shared__ float As[8][128];
    __shared__ float Bs[8][128];
    float acc[8][8];
    #pragma unroll
    for (int i = 0; i < 8; i++)
        #pragma unroll
        for (int j = 0; j < 8; j++) acc[i][j] = 0.f;
    const int tid = threadIdx.x;
    const int tx = tid & 15, ty = tid >> 4;
    const int am = tid >> 1, ak = (tid & 1)*4;
    const int bk = tid >> 5, bn = (tid & 31)*4;
    for (int kk = 0; kk < H_; kk += 8) {
        float4 av = *(const float4*)&g_rel[(row0+am)*H_ + kk + ak];
        float4 bv = *(const float4*)&W[(H_ + kk + bk)*EMB_ + nb + bn];
        __syncthreads();
        As[ak+0][am] = av.x; As[ak+1][am] = av.y;
        As[ak+2][am] = av.z; As[ak+3][am] = av.w;
        *(float4*)&Bs[bk][bn] = bv;
        __syncthreads();
        #pragma unroll
        for (int k = 0; k < 8; k++) {
            float4 a0 = *(const float4*)&As[k][ty*8];
            float4 a1 = *(const float4*)&As[k][ty*8+4];
            float4 b0 = *(const float4*)&Bs[k][tx*8];
            float4 b1 = *(const float4*)&Bs[k][tx*8+4];
            float ar[8] = {a0.x,a0.y,a0.z,a0.w,a1.x,a1.y,a1.z,a1.w};
            float br[8] = {b0.x,b0.y,b0.z,b0.w,b1.x,b1.y,b1.z,b1.w};
            #pragma unroll
            for (int i = 0; i < 8; i++)
                #pragma unroll
                for (int j = 0; j < 8; j++)
                    acc[i][j] += ar[i]*br[j];
        }
    }
    const float* Hx = head ? g_Hh : g_Ht;
    const float* bias = head ? bh : bt;
    float* outbuf = head ? g_he : g_te;
    #pragma unroll
    for (int i = 0; i < 8; i++) {
        int m = row0 + ty*8 + i;
        int b = m >> 9;
        int eidx = hts[m*2 + (head ? 0 : 1)];
        const float* hrow = Hx + (b*E_ + eidx)*EMB_;
        #pragma unroll
        for (int j = 0; j < 8; j++) {
            int n = nb + tx*8 + j;
            outbuf[m*EMB_ + n] = tanhf(acc[i][j] + hrow[n] + bias[n]);
        }
    }
}

// ---------------- K6: Wbc = Wb @ Wc (49152x768x97, padded N=128) -------------
__global__ void k_wbc(const float* __restrict__ Wb, const float* __restrict__ Wc) {
    const int row0 = blockIdx.x*128;
    __shared__ float As[8][128];
    __shared__ float Bs[8][128];
    float acc[8][8];
    #pragma unroll
    for (int i = 0; i < 8; i++)
        #pragma unroll
        for (int j = 0; j < 8; j++) acc[i][j] = 0.f;
    const int tid = threadIdx.x;
    const int tx = tid & 15, ty = tid >> 4;
    const int am = tid >> 1, ak = (tid & 1)*4;
    const int bk = tid >> 5, bn = (tid & 31)*4;
    for (int kk = 0; kk < EMB_; kk += 8) {
        float4 av = *(const float4*)&Wb[(row0+am)*EMB_ + kk + ak];
        float bsc[4];
        #pragma unroll
        for (int q = 0; q < 4; q++) {
            int n = bn + q;
            bsc[q] = (n < NCLS_) ? Wc[(kk+bk)*NCLS_ + n] : 0.f;
        }
        __syncthreads();
        As[ak+0][am] = av.x; As[ak+1][am] = av.y;
        As[ak+2][am] = av.z; As[ak+3][am] = av.w;
        Bs[bk][bn+0] = bsc[0]; Bs[bk][bn+1] = bsc[1];
        Bs[bk][bn+2] = bsc[2]; Bs[bk][bn+3] = bsc[3];
        __syncthreads();
        #pragma unroll
        for (int k = 0; k < 8; k++) {
            float4 a0 = *(const float4*)&As[k][ty*8];
            float4 a1 = *(const float4*)&As[k][ty*8+4];
            float4 b0 = *(const float4*)&Bs[k][tx*8];
            float4 b1 = *(const float4*)&Bs[k][tx*8+4];
            float ar[8] = {a0.x,a0.y,a0.z,a0.w,a1.x,a1.y,a1.z,a1.w};
            float br[8] = {b0.x,b0.y,b0.z,b0.w,b1.x,b1.y,b1.z,b1.w};
            #pragma unroll
            for (int i = 0; i < 8; i++)
                #pragma unroll
                for (int j = 0; j < 8; j++)
                    acc[i][j] += ar[i]*br[j];
        }
    }
    #pragma unroll
    for (int i = 0; i < 8; i++) {
        int m = row0 + ty*8 + i;
        #pragma unroll
        for (int j = 0; j < 8; j += 4) {
            float4 v = make_float4(acc[i][j],acc[i][j+1],acc[i][j+2],acc[i][j+3]);
            *(float4*)&g_Wbc[m*WLD_ + tx*8 + j] = v;
        }
    }
}

// ---------------- K7: bilinear classifier partials ---------------------------
// block: 64 rows x 112 cols (97 used), one k-block of 12; K-dim = 4096 (i,j)
__global__ void k_bilinear() {
    const int k = blockIdx.x;         // 0..11
    const int row0 = blockIdx.y*64;   // 32 row blocks
    __shared__ float he_s[64][64];
    __shared__ float te_t[64][72];    // [j][m], padded
    __shared__ float Bs[8][116];
    const int tid = threadIdx.x;
    const int tx = tid & 15, ty = tid >> 4;  // cols tx*7.., rows ty*4..
    // load he (row-major) and te (transposed)
    #pragma unroll
    for (int q = 0; q < 4; q++) {
        int idx = q*256 + tid;        // 0..1023 float4 slots
        int m = idx >> 4, c4 = (idx & 15)*4;
        float4 hv = *(const float4*)&g_he[(row0+m)*EMB_ + k*64 + c4];
        float4 tv = *(const float4*)&g_te[(row0+m)*EMB_ + k*64 + c4];
        *(float4*)&he_s[m][c4] = hv;
        te_t[c4+0][m] = tv.x; te_t[c4+1][m] = tv.y;
        te_t[c4+2][m] = tv.z; te_t[c4+3][m] = tv.w;
    }
    __syncthreads();
    float acc[4][7];
    #pragma unroll
    for (int r = 0; r < 4; r++)
        #pragma unroll
        for (int c = 0; c < 7; c++) acc[r][c] = 0.f;
    const int myrow = ty*4;
    for (int i = 0; i < 64; i++) {
        float hev[4];
        #pragma unroll
        for (int r = 0; r < 4; r++) hev[r] = he_s[myrow+r][i];
        for (int j0 = 0; j0 < 64; j0 += 8) {
            __syncthreads();
            if (tid < 224) {
                int rr = tid / 28, c4 = (tid % 28)*4;
                const float* src = g_Wbc + (k*4096 + i*64 + j0 + rr)*WLD_;
                *(float4*)&Bs[rr][c4] = *(const float4*)&src[c4];
            }
            __syncthreads();
            #pragma unroll
            for (int s = 0; s < 8; s++) {
                float bv[7];
                #pragma unroll
                for (int c = 0; c < 7; c++) bv[c] = Bs[s][tx*7 + c];
                float4 t4 = *(const float4*)&te_t[j0+s][myrow];
                float tr[4] = {t4.x, t4.y, t4.z, t4.w};
                #pragma unroll
                for (int r = 0; r < 4; r++) {
                    float a = hev[r] * tr[r];
                    #pragma unroll
                    for (int c = 0; c < 7; c++)
                        acc[r][c] += a * bv[c];
                }
            }
        }
    }
    #pragma unroll
    for (int r = 0; r < 4; r++) {
        int m = row0 + myrow + r;
        #pragma unroll
        for (int c = 0; c < 7; c++) {
            int n = tx*7 + c;
            if (n < NCLS_)
                g_part[(k*BR_ + m)*NCLS_ + n] = acc[r][c];
        }
    }
}

// ---------------- K8: reduce partials + bbc ----------------------------------
__global__ void k_reduce(float* __restrict__ out) {
    int idx = blockIdx.x*256 + threadIdx.x;
    if (idx < BR_*NCLS_) {
        int n = idx % NCLS_;
        float a = g_bbc[n];
        #pragma unroll
        for (int k = 0; k < KB_; k++) a += g_part[k*BR_*NCLS_ + idx];
        out[idx] = a;
    }
}

// ---------------- launch -----------------------------------------------------
extern "C" void kernel_launch(void* const* d_in, const int* in_sizes, int n_in,
                              void* d_out, int out_size) {
    const float* seq    = (const float*)d_in[0];
    const float* ent    = (const float*)d_in[1];
    const float* attn   = (const float*)d_in[2];
    const int*   labels = (const int*)  d_in[3];
    const int*   hts    = (const int*)  d_in[4];
    const float* Wh     = (const float*)d_in[5];
    const float* bh     = (const float*)d_in[6];
    const float* Wt     = (const float*)d_in[7];
    const float* bt     = (const float*)d_in[8];
    const float* Wb     = (const float*)d_in[9];
    const float* bb     = (const float*)d_in[10];
    const float* Wc     = (const float*)d_in[11];
    const float* bc     = (const float*)d_in[12];
    float* out = (float*)d_out;

    k_prep<<<1, 128>>>(labels);
    k_bbc<<<1, 128>>>(bb, Wc, bc);
    k_entemb<<<B_*E_, 128>>>(ent);
    k_entattn<<<dim3(B_*E_, NH_), 256>>>(attn);
    k_ht<<<BR_, 256>>>(hts);
    k_rel<<<dim3(H_/128, R_/128, B_), 256>>>(seq);
    k_hx<<<dim3(EMB_/128, 3, 2), 256>>>(Wh, Wt);
    k_hete<<<dim3(12, 16), 256>>>(Wh, Wt, bh, bt, hts);
    k_wbc<<<WROWS_/128, 256>>>(Wb, Wc);
    k_bilinear<<<dim3(KB_, BR_/64), 256>>>();
    k_reduce<<<(BR_*NCLS_ + 255)/256, 256>>>(out);
}

// round 2
// speedup vs baseline: 2.0018x; 2.0018x over previous
#include <cuda_runtime.h>
#include <math.h>
#include <stdint.h>

#define B_ 4
#define L_ 1024
#define H_ 1024
#define NH_ 16
#define M_ 64
#define E_ 24
#define R_ 512
#define EMB_ 768
#define NCLS_ 97
#define KB_ 12            // EMB / 64
#define BR_ 2048          // B*R
#define WROWS_ 49152      // EMB*64
#define WLD_ 128          // padded N stride for Wbc / partials

// ---------------- scratch (static device globals; no allocation) -------------
__device__ int   g_cnt[B_*E_];
__device__ int   g_mlist[B_*E_*M_];
__device__ float g_entemb[B_*E_*H_];
__device__ float g_entattn[B_*E_*NH_*L_];
__device__ float g_ht[B_*R_*L_];
__device__ float g_rel[B_*R_*H_];
__device__ float g_he[BR_*EMB_];
__device__ float g_te[BR_*EMB_];
__device__ float g_Hh[B_*E_*EMB_];
__device__ float g_Ht[B_*E_*EMB_];
__device__ float g_Wbc[WROWS_*WLD_];
__device__ float g_part[KB_*BR_*WLD_];
__device__ float g_bbc[NCLS_];

// ---------------- tf32 helpers ----------------------------------------------
__device__ __forceinline__ float tf(float x) {
    float r;
    asm("cvt.rna.tf32.f32 %0, %1;" : "=f"(r) : "f"(x));
    return r;
}
__device__ __forceinline__ void mma8(float c[4], const uint32_t a[4],
                                     uint32_t b0, uint32_t b1) {
    asm volatile(
        "mma.sync.aligned.m16n8k8.row.col.f32.tf32.tf32.f32 "
        "{%0,%1,%2,%3}, {%4,%5,%6,%7}, {%8,%9}, {%0,%1,%2,%3};\n"
        : "+f"(c[0]), "+f"(c[1]), "+f"(c[2]), "+f"(c[3])
        : "r"(a[0]), "r"(a[1]), "r"(a[2]), "r"(a[3]), "r"(b0), "r"(b1));
}
#define FU(x) __float_as_uint(x)

// ---------------- K0: mention lists per (b,e) --------------------------------
__global__ void k_prep(const int* __restrict__ labels) {
    int t = threadIdx.x;
    if (t < B_*E_) {
        int b = t / E_, e = t % E_;
        int c = 0;
        for (int m = 0; m < M_; m++)
            if (labels[b*M_ + m] == e) g_mlist[t*M_ + c++] = m;
        g_cnt[t] = c;
    }
}

// ---------------- bbc = bb @ Wc + bc ----------------------------------------
__global__ void k_bbc(const float* __restrict__ bb, const float* __restrict__ Wc,
                      const float* __restrict__ bc) {
    int n = threadIdx.x;
    if (n < NCLS_) {
        float a = bc[n];
        for (int d = 0; d < EMB_; d++) a += bb[d] * Wc[d*NCLS_ + n];
        g_bbc[n] = a;
    }
}

// ---------------- K1: entity logsumexp pooling -------------------------------
__global__ void k_entemb(const float* __restrict__ ent) {
    int be = blockIdx.x;
    int b = be / E_;
    __shared__ int lst[M_];
    __shared__ int scnt;
    if (threadIdx.x == 0) scnt = g_cnt[be];
    __syncthreads();
    int cnt = scnt;
    if (threadIdx.x < cnt) lst[threadIdx.x] = g_mlist[be*M_ + threadIdx.x];
    __syncthreads();
    for (int h = threadIdx.x; h < H_; h += blockDim.x) {
        float o = 0.f;
        if (cnt > 0) {
            float mx = -3.4e38f;
            for (int c = 0; c < cnt; c++)
                mx = fmaxf(mx, ent[(b*M_ + lst[c])*H_ + h]);
            float s = 0.f;
            for (int c = 0; c < cnt; c++)
                s += expf(ent[(b*M_ + lst[c])*H_ + h] - mx);
            o = mx + logf(s);
        }
        g_entemb[be*H_ + h] = o;
    }
}

// ---------------- K2: entity->seq attention (mean over mentions) -------------
__global__ void k_entattn(const float* __restrict__ attn) {
    int be = blockIdx.x, nh = blockIdx.y;
    int b = be / E_;
    __shared__ int lst[M_];
    __shared__ int scnt;
    if (threadIdx.x == 0) scnt = g_cnt[be];
    __syncthreads();
    int cnt = scnt;
    if (threadIdx.x < cnt) lst[threadIdx.x] = g_mlist[be*M_ + threadIdx.x];
    __syncthreads();
    float inv = 1.f / (float)(cnt > 1 ? cnt : 1);
    const float* base = attn + (b*NH_ + nh)*M_*L_;
    float* outp = g_entattn + (be*NH_ + nh)*L_;
    for (int l = threadIdx.x; l < L_; l += blockDim.x) {
        float a = 0.f;
        for (int c = 0; c < cnt; c++) a += base[lst[c]*L_ + l];
        outp[l] = a * inv;
    }
}

// ---------------- K3: pair attention product + normalize ---------------------
__global__ void k_ht(const int* __restrict__ hts) {
    int br = blockIdx.x;
    int b = br >> 9;
    int h = hts[br*2 + 0], t = hts[br*2 + 1];
    const float* ph = g_entattn + (b*E_ + h)*NH_*L_;
    const float* pt = g_entattn + (b*E_ + t)*NH_*L_;
    float v[4];
    float lsum = 0.f;
    #pragma unroll
    for (int q = 0; q < 4; q++) {
        int l = threadIdx.x + q*256;
        float s = 0.f;
        #pragma unroll
        for (int nh = 0; nh < NH_; nh++)
            s += ph[nh*L_ + l] * pt[nh*L_ + l];
        v[q] = s * (1.f/NH_);
        lsum += v[q];
    }
    __shared__ float red[256];
    red[threadIdx.x] = lsum;
    __syncthreads();
    for (int s = 128; s > 0; s >>= 1) {
        if (threadIdx.x < s) red[threadIdx.x] += red[threadIdx.x + s];
        __syncthreads();
    }
    float inv = 1.f / (red[0] + 1e-5f);
    #pragma unroll
    for (int q = 0; q < 4; q++) {
        int l = threadIdx.x + q*256;
        g_ht[br*L_ + l] = v[q] * inv;
    }
}

// ---------------- K4: rel = ht @ seq (tf32 mma, per-batch 512x1024x1024) -----
__global__ void k_rel_mma(const float* __restrict__ seq) {
    const int b = blockIdx.z;
    const float* A = g_ht + b*R_*L_;
    const float* Bm = seq + b*L_*H_;
    float* C = g_rel + b*R_*H_;
    const int row0 = blockIdx.y*128, col0 = blockIdx.x*128;
    __shared__ float As[16][132];
    __shared__ float Bs[16][132];
    const int tid = threadIdx.x;
    const int lane = tid & 31, wid = tid >> 5;
    const int g = lane >> 2, tc = lane & 3;
    const int wm = (wid >> 1)*32, wn = (wid & 1)*64;
    float acc[2][8][4];
    #pragma unroll
    for (int i = 0; i < 2; i++)
        #pragma unroll
        for (int j = 0; j < 8; j++)
            #pragma unroll
            for (int c = 0; c < 4; c++) acc[i][j][c] = 0.f;
    const int am = tid >> 1, ak = (tid & 1)*8;
    const int bk = tid >> 4, bn = (tid & 15)*8;
    for (int kk = 0; kk < L_; kk += 16) {
        float4 a0 = *(const float4*)&A[(row0+am)*L_ + kk + ak];
        float4 a1 = *(const float4*)&A[(row0+am)*L_ + kk + ak + 4];
        float4 b0 = *(const float4*)&Bm[(kk+bk)*H_ + col0 + bn];
        float4 b1 = *(const float4*)&Bm[(kk+bk)*H_ + col0 + bn + 4];
        __syncthreads();
        As[ak+0][am]=tf(a0.x); As[ak+1][am]=tf(a0.y);
        As[ak+2][am]=tf(a0.z); As[ak+3][am]=tf(a0.w);
        As[ak+4][am]=tf(a1.x); As[ak+5][am]=tf(a1.y);
        As[ak+6][am]=tf(a1.z); As[ak+7][am]=tf(a1.w);
        *(float4*)&Bs[bk][bn]   = make_float4(tf(b0.x),tf(b0.y),tf(b0.z),tf(b0.w));
        *(float4*)&Bs[bk][bn+4] = make_float4(tf(b1.x),tf(b1.y),tf(b1.z),tf(b1.w));
        __syncthreads();
        #pragma unroll
        for (int k8 = 0; k8 < 16; k8 += 8) {
            uint32_t af[2][4];
            #pragma unroll
            for (int mt = 0; mt < 2; mt++) {
                int mr = wm + mt*16 + g;
                af[mt][0] = FU(As[k8+tc][mr]);
                af[mt][1] = FU(As[k8+tc][mr+8]);
                af[mt][2] = FU(As[k8+tc+4][mr]);
                af[mt][3] = FU(As[k8+tc+4][mr+8]);
            }
            #pragma unroll
            for (int nt = 0; nt < 8; nt++) {
                int n = wn + nt*8 + g;
                uint32_t bf0 = FU(Bs[k8+tc][n]);
                uint32_t bf1 = FU(Bs[k8+tc+4][n]);
                mma8(acc[0][nt], af[0], bf0, bf1);
                mma8(acc[1][nt], af[1], bf0, bf1);
            }
        }
    }
    #pragma unroll
    for (int mt = 0; mt < 2; mt++) {
        int m = row0 + wm + mt*16 + g;
        #pragma unroll
        for (int nt = 0; nt < 8; nt++) {
            int n = col0 + wn + nt*8 + 2*tc;
            *(float2*)&C[m*H_ + n]     = make_float2(acc[mt][nt][0], acc[mt][nt][1]);
            *(float2*)&C[(m+8)*H_ + n] = make_float2(acc[mt][nt][2], acc[mt][nt][3]);
        }
    }
}

// ---------------- K5a: Hh/Ht = ent_emb @ W*_top (96x1024x768 x2, fp32) -------
__global__ void k_hx(const float* __restrict__ Wh, const float* __restrict__ Wt) {
    const int z = blockIdx.z;
    const float* W = z ? Wt : Wh;
    float* Cout = z ? g_Ht : g_Hh;
    const int row0 = blockIdx.y*32, col0 = blockIdx.x*128;
    __shared__ float As[16][32];
    __shared__ float Bs[16][128];
    float acc[2][8];
    #pragma unroll
    for (int i = 0; i < 2; i++)
        #pragma unroll
        for (int j = 0; j < 8; j++) acc[i][j] = 0.f;
    const int tid = threadIdx.x;
    const int tx = tid & 15, ty = tid >> 4;
    for (int kk = 0; kk < H_; kk += 16) {
        __syncthreads();
        if (tid < 128) {
            int m = tid >> 2, k4 = (tid & 3)*4;
            float4 av = *(const float4*)&g_entemb[(row0+m)*H_ + kk + k4];
            As[k4+0][m] = av.x; As[k4+1][m] = av.y;
            As[k4+2][m] = av.z; As[k4+3][m] = av.w;
        }
        #pragma unroll
        for (int q = 0; q < 2; q++) {
            int idx = q*256 + tid;
            int k = idx >> 5, n4 = (idx & 31)*4;
            *(float4*)&Bs[k][n4] = *(const float4*)&W[(kk+k)*EMB_ + col0 + n4];
        }
        __syncthreads();
        #pragma unroll
        for (int k = 0; k < 16; k++) {
            float a0 = As[k][ty*2], a1 = As[k][ty*2+1];
            float4 b0 = *(const float4*)&Bs[k][tx*8];
            float4 b1 = *(const float4*)&Bs[k][tx*8+4];
            float br[8] = {b0.x,b0.y,b0.z,b0.w,b1.x,b1.y,b1.z,b1.w};
            #pragma unroll
            for (int j = 0; j < 8; j++) {
                acc[0][j] += a0*br[j];
                acc[1][j] += a1*br[j];
            }
        }
    }
    #pragma unroll
    for (int i = 0; i < 2; i++) {
        int m = row0 + ty*2 + i;
        #pragma unroll
        for (int j = 0; j < 8; j += 4) {
            float4 v = make_float4(acc[i][j],acc[i][j+1],acc[i][j+2],acc[i][j+3]);
            *(float4*)&Cout[m*EMB_ + col0 + tx*8 + j] = v;
        }
    }
}

// ---------------- K5b: he/te = tanh(rel @ W*_bot + Hx + b) (tf32 mma) --------
__global__ void k_hete_mma(const float* __restrict__ Wh, const float* __restrict__ Wt,
                           const float* __restrict__ bh, const float* __restrict__ bt,
                           const int* __restrict__ hts) {
    const int col0 = blockIdx.x*128, row0 = blockIdx.y*128;
    const bool head = (col0 < EMB_);
    const float* W = head ? Wh : Wt;
    const int nb = head ? col0 : col0 - EMB_;
    __shared__ float As[16][132];
    __shared__ float Bs[16][132];
    const int tid = threadIdx.x;
    const int lane = tid & 31, wid = tid >> 5;
    const int g = lane >> 2, tc = lane & 3;
    const int wm = (wid >> 1)*32, wn = (wid & 1)*64;
    float acc[2][8][4];
    #pragma unroll
    for (int i = 0; i < 2; i++)
        #pragma unroll
        for (int j = 0; j < 8; j++)
            #pragma unroll
            for (int c = 0; c < 4; c++) acc[i][j][c] = 0.f;
    const int am = tid >> 1, ak = (tid & 1)*8;
    const int bk = tid >> 4, bn = (tid & 15)*8;
    for (int kk = 0; kk < H_; kk += 16) {
        float4 a0 = *(const float4*)&g_rel[(row0+am)*H_ + kk + ak];
        float4 a1 = *(const float4*)&g_rel[(row0+am)*H_ + kk + ak + 4];
        float4 b0 = *(const float4*)&W[(H_ + kk + bk)*EMB_ + nb + bn];
        float4 b1 = *(const float4*)&W[(H_ + kk + bk)*EMB_ + nb + bn + 4];
        __syncthreads();
        As[ak+0][am]=tf(a0.x); As[ak+1][am]=tf(a0.y);
        As[ak+2][am]=tf(a0.z); As[ak+3][am]=tf(a0.w);
        As[ak+4][am]=tf(a1.x); As[ak+5][am]=tf(a1.y);
        As[ak+6][am]=tf(a1.z); As[ak+7][am]=tf(a1.w);
        *(float4*)&Bs[bk][bn]   = make_float4(tf(b0.x),tf(b0.y),tf(b0.z),tf(b0.w));
        *(float4*)&Bs[bk][bn+4] = make_float4(tf(b1.x),tf(b1.y),tf(b1.z),tf(b1.w));
        __syncthreads();
        #pragma unroll
        for (int k8 = 0; k8 < 16; k8 += 8) {
            uint32_t af[2][4];
            #pragma unroll
            for (int mt = 0; mt < 2; mt++) {
                int mr = wm + mt*16 + g;
                af[mt][0] = FU(As[k8+tc][mr]);
                af[mt][1] = FU(As[k8+tc][mr+8]);
                af[mt][2] = FU(As[k8+tc+4][mr]);
                af[mt][3] = FU(As[k8+tc+4][mr+8]);
            }
            #pragma unroll
            for (int nt = 0; nt < 8; nt++) {
                int n = wn + nt*8 + g;
                uint32_t bf0 = FU(Bs[k8+tc][n]);
                uint32_t bf1 = FU(Bs[k8+tc+4][n]);
                mma8(acc[0][nt], af[0], bf0, bf1);
                mma8(acc[1][nt], af[1], bf0, bf1);
            }
        }
    }
    const float* Hx = head ? g_Hh : g_Ht;
    const float* bias = head ? bh : bt;
    float* outbuf = head ? g_he : g_te;
    #pragma unroll
    for (int mt = 0; mt < 2; mt++) {
        #pragma unroll
        for (int half = 0; half < 2; half++) {
            int m = row0 + wm + mt*16 + g + half*8;
            int b = m >> 9;
            int eidx = hts[m*2 + (head ? 0 : 1)];
            const float* hrow = Hx + (b*E_ + eidx)*EMB_;
            #pragma unroll
            for (int nt = 0; nt < 8; nt++) {
                int n = nb + wn + nt*8 + 2*tc;
                outbuf[m*EMB_ + n]   = tanhf(acc[mt][nt][2*half+0] + hrow[n]   + bias[n]);
                outbuf[m*EMB_ + n+1] = tanhf(acc[mt][nt][2*half+1] + hrow[n+1] + bias[n+1]);
            }
        }
    }
}

// ---------------- K6: Wbc = Wb @ Wc (49152x768x97, tf32 mma, N padded 128) ---
__global__ void k_wbc_mma(const float* __restrict__ Wb, const float* __restrict__ Wc) {
    const int row0 = blockIdx.x*128;
    __shared__ float As[16][132];
    __shared__ float Bs[16][132];
    const int tid = threadIdx.x;
    const int lane = tid & 31, wid = tid >> 5;
    const int g = lane >> 2, tc = lane & 3;
    const int wm = (wid >> 1)*32, wn = (wid & 1)*64;
    float acc[2][8][4];
    #pragma unroll
    for (int i = 0; i < 2; i++)
        #pragma unroll
        for (int j = 0; j < 8; j++)
            #pragma unroll
            for (int c = 0; c < 4; c++) acc[i][j][c] = 0.f;
    const int am = tid >> 1, ak = (tid & 1)*8;
    const int bk = tid >> 4, bn = (tid & 15)*8;
    for (int kk = 0; kk < EMB_; kk += 16) {
        float4 a0 = *(const float4*)&Wb[(row0+am)*EMB_ + kk + ak];
        float4 a1 = *(const float4*)&Wb[(row0+am)*EMB_ + kk + ak + 4];
        float bv[8];
        #pragma unroll
        for (int q = 0; q < 8; q++) {
            int n = bn + q;
            bv[q] = (n < NCLS_) ? tf(Wc[(kk+bk)*NCLS_ + n]) : 0.f;
        }
        __syncthreads();
        As[ak+0][am]=tf(a0.x); As[ak+1][am]=tf(a0.y);
        As[ak+2][am]=tf(a0.z); As[ak+3][am]=tf(a0.w);
        As[ak+4][am]=tf(a1.x); As[ak+5][am]=tf(a1.y);
        As[ak+6][am]=tf(a1.z); As[ak+7][am]=tf(a1.w);
        #pragma unroll
        for (int q = 0; q < 8; q++) Bs[bk][bn+q] = bv[q];
        __syncthreads();
        #pragma unroll
        for (int k8 = 0; k8 < 16; k8 += 8) {
            uint32_t af[2][4];
            #pragma unroll
            for (int mt = 0; mt < 2; mt++) {
                int mr = wm + mt*16 + g;
                af[mt][0] = FU(As[k8+tc][mr]);
                af[mt][1] = FU(As[k8+tc][mr+8]);
                af[mt][2] = FU(As[k8+tc+4][mr]);
                af[mt][3] = FU(As[k8+tc+4][mr+8]);
            }
            #pragma unroll
            for (int nt = 0; nt < 8; nt++) {
                int n = wn + nt*8 + g;
                uint32_t bf0 = FU(Bs[k8+tc][n]);
                uint32_t bf1 = FU(Bs[k8+tc+4][n]);
                mma8(acc[0][nt], af[0], bf0, bf1);
                mma8(acc[1][nt], af[1], bf0, bf1);
            }
        }
    }
    #pragma unroll
    for (int mt = 0; mt < 2; mt++) {
        int m = row0 + wm + mt*16 + g;
        #pragma unroll
        for (int nt = 0; nt < 8; nt++) {
            int n = wn + nt*8 + 2*tc;
            *(float2*)&g_Wbc[m*WLD_ + n]     = make_float2(acc[mt][nt][0], acc[mt][nt][1]);
            *(float2*)&g_Wbc[(m+8)*WLD_ + n] = make_float2(acc[mt][nt][2], acc[mt][nt][3]);
        }
    }
}

// ---------------- K7: bilinear classifier via virtual-A tf32 GEMM ------------
// grid (kb=12, rowblock=16); block computes 128 rows x 128 cols over K=4096
// A[m][i*64+j] = he[m][kb*64+i] * te[m][kb*64+j]  (generated from smem)
#define BIL_SMEM ((64*132 + 128*65 + 64*132)*4)
__global__ void k_bilinear_mma() {
    extern __shared__ float sm[];
    float (*te_t)[132] = (float(*)[132])sm;                    // [j][m]
    float (*he_s)[65]  = (float(*)[65])(sm + 64*132);          // [m][i]
    float (*Bs)[132]   = (float(*)[132])(sm + 64*132 + 128*65);// [j][n]
    const int kb = blockIdx.x;
    const int row0 = blockIdx.y*128;
    const int tid = threadIdx.x;
    const int lane = tid & 31, wid = tid >> 5;
    const int g = lane >> 2, tc = lane & 3;
    const int wm = (wid >> 1)*32, wn = (wid & 1)*64;
    // load he/te tiles (128 x 64 each)
    #pragma unroll
    for (int q = 0; q < 8; q++) {
        int idx = q*256 + tid;
        int m = idx >> 4, c4 = (idx & 15)*4;
        float4 hv = *(const float4*)&g_he[(row0+m)*EMB_ + kb*64 + c4];
        float4 tv = *(const float4*)&g_te[(row0+m)*EMB_ + kb*64 + c4];
        he_s[m][c4+0]=tf(hv.x); he_s[m][c4+1]=tf(hv.y);
        he_s[m][c4+2]=tf(hv.z); he_s[m][c4+3]=tf(hv.w);
        te_t[c4+0][m]=tf(tv.x); te_t[c4+1][m]=tf(tv.y);
        te_t[c4+2][m]=tf(tv.z); te_t[c4+3][m]=tf(tv.w);
    }
    float acc[2][8][4];
    #pragma unroll
    for (int i = 0; i < 2; i++)
        #pragma unroll
        for (int j = 0; j < 8; j++)
            #pragma unroll
            for (int c = 0; c < 4; c++) acc[i][j][c] = 0.f;
    for (int i = 0; i < 64; i++) {
        __syncthreads();
        // stage 64x128 Wbc rows for this (kb, i)
        #pragma unroll
        for (int q = 0; q < 8; q++) {
            int idx = q*256 + tid;
            int j = idx >> 5, n4 = (idx & 31)*4;
            float4 wv = *(const float4*)&g_Wbc[(kb*4096 + i*64 + j)*WLD_ + n4];
            *(float4*)&Bs[j][n4] = make_float4(tf(wv.x),tf(wv.y),tf(wv.z),tf(wv.w));
        }
        __syncthreads();
        float h[2][2];
        #pragma unroll
        for (int mt = 0; mt < 2; mt++) {
            h[mt][0] = he_s[wm + mt*16 + g][i];
            h[mt][1] = he_s[wm + mt*16 + g + 8][i];
        }
        #pragma unroll
        for (int j8 = 0; j8 < 8; j8++) {
            uint32_t af[2][4];
            #pragma unroll
            for (int mt = 0; mt < 2; mt++) {
                int mr = wm + mt*16 + g;
                af[mt][0] = FU(tf(te_t[j8*8+tc][mr]     * h[mt][0]));
                af[mt][1] = FU(tf(te_t[j8*8+tc][mr+8]   * h[mt][1]));
                af[mt][2] = FU(tf(te_t[j8*8+tc+4][mr]   * h[mt][0]));
                af[mt][3] = FU(tf(te_t[j8*8+tc+4][mr+8] * h[mt][1]));
            }
            #pragma unroll
            for (int nt = 0; nt < 8; nt++) {
                int n = wn + nt*8 + g;
                uint32_t bf0 = FU(Bs[j8*8+tc][n]);
                uint32_t bf1 = FU(Bs[j8*8+tc+4][n]);
                mma8(acc[0][nt], af[0], bf0, bf1);
                mma8(acc[1][nt], af[1], bf0, bf1);
            }
        }
    }
    #pragma unroll
    for (int mt = 0; mt < 2; mt++) {
        int m = row0 + wm + mt*16 + g;
        #pragma unroll
        for (int nt = 0; nt < 8; nt++) {
            int n = wn + nt*8 + 2*tc;
            *(float2*)&g_part[(kb*BR_ + m)*WLD_ + n]     = make_float2(acc[mt][nt][0], acc[mt][nt][1]);
            *(float2*)&g_part[(kb*BR_ + m + 8)*WLD_ + n] = make_float2(acc[mt][nt][2], acc[mt][nt][3]);
        }
    }
}

// ---------------- K8: reduce partials + bbc ----------------------------------
__global__ void k_reduce(float* __restrict__ out) {
    int idx = blockIdx.x*256 + threadIdx.x;
    if (idx < BR_*NCLS_) {
        int r = idx / NCLS_, n = idx % NCLS_;
        float a = g_bbc[n];
        #pragma unroll
        for (int k = 0; k < KB_; k++) a += g_part[(k*BR_ + r)*WLD_ + n];
        out[idx] = a;
    }
}

// ---------------- launch -----------------------------------------------------
extern "C" void kernel_launch(void* const* d_in, const int* in_sizes, int n_in,
                              void* d_out, int out_size) {
    const float* seq    = (const float*)d_in[0];
    const float* ent    = (const float*)d_in[1];
    const float* attn   = (const float*)d_in[2];
    const int*   labels = (const int*)  d_in[3];
    const int*   hts    = (const int*)  d_in[4];
    const float* Wh     = (const float*)d_in[5];
    const float* bh     = (const float*)d_in[6];
    const float* Wt     = (const float*)d_in[7];
    const float* bt     = (const float*)d_in[8];
    const float* Wb     = (const float*)d_in[9];
    const float* bb     = (const float*)d_in[10];
    const float* Wc     = (const float*)d_in[11];
    const float* bc     = (const float*)d_in[12];
    float* out = (float*)d_out;

    cudaFuncSetAttribute(k_bilinear_mma,
                         cudaFuncAttributeMaxDynamicSharedMemorySize, BIL_SMEM);

    k_prep<<<1, 128>>>(labels);
    k_bbc<<<1, 128>>>(bb, Wc, bc);
    k_entemb<<<B_*E_, 128>>>(ent);
    k_entattn<<<dim3(B_*E_, NH_), 256>>>(attn);
    k_ht<<<BR_, 256>>>(hts);
    k_rel_mma<<<dim3(H_/128, R_/128, B_), 256>>>(seq);
    k_hx<<<dim3(EMB_/128, 3, 2), 256>>>(Wh, Wt);
    k_hete_mma<<<dim3(12, 16), 256>>>(Wh, Wt, bh, bt, hts);
    k_wbc_mma<<<WROWS_/128, 256>>>(Wb, Wc);
    k_bilinear_mma<<<dim3(KB_, 16), 256, BIL_SMEM>>>();
    k_reduce<<<(BR_*NCLS_ + 255)/256, 256>>>(out);
}

// round 3
// speedup vs baseline: 2.0167x; 1.0074x over previous
#include <cuda_runtime.h>
#include <math.h>
#include <stdint.h>

#define B_ 4
#define L_ 1024
#define H_ 1024
#define NH_ 16
#define M_ 64
#define E_ 24
#define R_ 512
#define EMB_ 768
#define NCLS_ 97
#define KB_ 12            // EMB / 64
#define BR_ 2048          // B*R
#define WROWS_ 49152      // EMB*64
#define WLD_ 128          // padded N stride for Wbc / partials

// ---------------- scratch (static device globals; no allocation) -------------
__device__ int   g_cnt[B_*E_];
__device__ int   g_mlist[B_*E_*M_];
__device__ float g_entemb[B_*E_*H_];
__device__ float g_entattn[B_*E_*NH_*L_];
__device__ float g_ht[B_*R_*L_];
__device__ float g_rel[B_*R_*H_];
__device__ float g_he[BR_*EMB_];
__device__ float g_te[BR_*EMB_];
__device__ float g_Hh[B_*E_*EMB_];
__device__ float g_Ht[B_*E_*EMB_];
__device__ float g_Wbc[WROWS_*WLD_];
__device__ float g_part[KB_*BR_*WLD_];
__device__ float g_bbc[NCLS_];

// ---------------- tf32 helpers ----------------------------------------------
__device__ __forceinline__ float tf(float x) {
    float r;
    asm("cvt.rna.tf32.f32 %0, %1;" : "=f"(r) : "f"(x));
    return r;
}
__device__ __forceinline__ void mma8(float c[4], const uint32_t a[4],
                                     uint32_t b0, uint32_t b1) {
    asm volatile(
        "mma.sync.aligned.m16n8k8.row.col.f32.tf32.tf32.f32 "
        "{%0,%1,%2,%3}, {%4,%5,%6,%7}, {%8,%9}, {%0,%1,%2,%3};\n"
        : "+f"(c[0]), "+f"(c[1]), "+f"(c[2]), "+f"(c[3])
        : "r"(a[0]), "r"(a[1]), "r"(a[2]), "r"(a[3]), "r"(b0), "r"(b1));
}
#define FU(x) __float_as_uint(x)

// ---------------- K0: mention lists per (b,e) --------------------------------
__global__ void k_prep(const int* __restrict__ labels) {
    int t = threadIdx.x;
    if (t < B_*E_) {
        int b = t / E_, e = t % E_;
        int c = 0;
        for (int m = 0; m < M_; m++)
            if (labels[b*M_ + m] == e) g_mlist[t*M_ + c++] = m;
        g_cnt[t] = c;
    }
}

// ---------------- bbc = bb @ Wc + bc ----------------------------------------
__global__ void k_bbc(const float* __restrict__ bb, const float* __restrict__ Wc,
                      const float* __restrict__ bc) {
    int n = threadIdx.x;
    if (n < NCLS_) {
        float a = bc[n];
        for (int d = 0; d < EMB_; d++) a += bb[d] * Wc[d*NCLS_ + n];
        g_bbc[n] = a;
    }
}

// ---------------- K1: entity logsumexp pooling -------------------------------
__global__ void k_entemb(const float* __restrict__ ent) {
    int be = blockIdx.x;
    int b = be / E_;
    __shared__ int lst[M_];
    __shared__ int scnt;
    if (threadIdx.x == 0) scnt = g_cnt[be];
    __syncthreads();
    int cnt = scnt;
    if (threadIdx.x < cnt) lst[threadIdx.x] = g_mlist[be*M_ + threadIdx.x];
    __syncthreads();
    for (int h = threadIdx.x; h < H_; h += blockDim.x) {
        float o = 0.f;
        if (cnt > 0) {
            float mx = -3.4e38f;
            for (int c = 0; c < cnt; c++)
                mx = fmaxf(mx, ent[(b*M_ + lst[c])*H_ + h]);
            float s = 0.f;
            for (int c = 0; c < cnt; c++)
                s += expf(ent[(b*M_ + lst[c])*H_ + h] - mx);
            o = mx + logf(s);
        }
        g_entemb[be*H_ + h] = o;
    }
}

// ---------------- K2: entity->seq attention (mean over mentions) -------------
__global__ void k_entattn(const float* __restrict__ attn) {
    int be = blockIdx.x, nh = blockIdx.y;
    int b = be / E_;
    __shared__ int lst[M_];
    __shared__ int scnt;
    if (threadIdx.x == 0) scnt = g_cnt[be];
    __syncthreads();
    int cnt = scnt;
    if (threadIdx.x < cnt) lst[threadIdx.x] = g_mlist[be*M_ + threadIdx.x];
    __syncthreads();
    float inv = 1.f / (float)(cnt > 1 ? cnt : 1);
    const float* base = attn + (b*NH_ + nh)*M_*L_;
    float* outp = g_entattn + (be*NH_ + nh)*L_;
    for (int l = threadIdx.x; l < L_; l += blockDim.x) {
        float a = 0.f;
        for (int c = 0; c < cnt; c++) a += base[lst[c]*L_ + l];
        outp[l] = a * inv;
    }
}

// ---------------- K3: pair attention product + normalize ---------------------
__global__ void k_ht(const int* __restrict__ hts) {
    int br = blockIdx.x;
    int b = br >> 9;
    int h = hts[br*2 + 0], t = hts[br*2 + 1];
    const float* ph = g_entattn + (b*E_ + h)*NH_*L_;
    const float* pt = g_entattn + (b*E_ + t)*NH_*L_;
    float v[4];
    float lsum = 0.f;
    #pragma unroll
    for (int q = 0; q < 4; q++) {
        int l = threadIdx.x + q*256;
        float s = 0.f;
        #pragma unroll
        for (int nh = 0; nh < NH_; nh++)
            s += ph[nh*L_ + l] * pt[nh*L_ + l];
        v[q] = s * (1.f/NH_);
        lsum += v[q];
    }
    __shared__ float red[256];
    red[threadIdx.x] = lsum;
    __syncthreads();
    for (int s = 128; s > 0; s >>= 1) {
        if (threadIdx.x < s) red[threadIdx.x] += red[threadIdx.x + s];
        __syncthreads();
    }
    float inv = 1.f / (red[0] + 1e-5f);
    #pragma unroll
    for (int q = 0; q < 4; q++) {
        int l = threadIdx.x + q*256;
        g_ht[br*L_ + l] = v[q] * inv;
    }
}

// ---------------- K4: rel = ht @ seq (tf32 mma, per-batch 512x1024x1024) -----
__global__ void k_rel_mma(const float* __restrict__ seq) {
    const int b = blockIdx.z;
    const float* A = g_ht + b*R_*L_;
    const float* Bm = seq + b*L_*H_;
    float* C = g_rel + b*R_*H_;
    const int row0 = blockIdx.y*128, col0 = blockIdx.x*128;
    __shared__ float As[16][132];
    __shared__ float Bs[16][132];
    const int tid = threadIdx.x;
    const int lane = tid & 31, wid = tid >> 5;
    const int g = lane >> 2, tc = lane & 3;
    const int wm = (wid >> 1)*32, wn = (wid & 1)*64;
    float acc[2][8][4];
    #pragma unroll
    for (int i = 0; i < 2; i++)
        #pragma unroll
        for (int j = 0; j < 8; j++)
            #pragma unroll
            for (int c = 0; c < 4; c++) acc[i][j][c] = 0.f;
    const int am = tid >> 1, ak = (tid & 1)*8;
    const int bk = tid >> 4, bn = (tid & 15)*8;
    for (int kk = 0; kk < L_; kk += 16) {
        float4 a0 = *(const float4*)&A[(row0+am)*L_ + kk + ak];
        float4 a1 = *(const float4*)&A[(row0+am)*L_ + kk + ak + 4];
        float4 b0 = *(const float4*)&Bm[(kk+bk)*H_ + col0 + bn];
        float4 b1 = *(const float4*)&Bm[(kk+bk)*H_ + col0 + bn + 4];
        __syncthreads();
        As[ak+0][am]=tf(a0.x); As[ak+1][am]=tf(a0.y);
        As[ak+2][am]=tf(a0.z); As[ak+3][am]=tf(a0.w);
        As[ak+4][am]=tf(a1.x); As[ak+5][am]=tf(a1.y);
        As[ak+6][am]=tf(a1.z); As[ak+7][am]=tf(a1.w);
        *(float4*)&Bs[bk][bn]   = make_float4(tf(b0.x),tf(b0.y),tf(b0.z),tf(b0.w));
        *(float4*)&Bs[bk][bn+4] = make_float4(tf(b1.x),tf(b1.y),tf(b1.z),tf(b1.w));
        __syncthreads();
        #pragma unroll
        for (int k8 = 0; k8 < 16; k8 += 8) {
            uint32_t af[2][4];
            #pragma unroll
            for (int mt = 0; mt < 2; mt++) {
                int mr = wm + mt*16 + g;
                af[mt][0] = FU(As[k8+tc][mr]);
                af[mt][1] = FU(As[k8+tc][mr+8]);
                af[mt][2] = FU(As[k8+tc+4][mr]);
                af[mt][3] = FU(As[k8+tc+4][mr+8]);
            }
            #pragma unroll
            for (int nt = 0; nt < 8; nt++) {
                int n = wn + nt*8 + g;
                uint32_t bf0 = FU(Bs[k8+tc][n]);
                uint32_t bf1 = FU(Bs[k8+tc+4][n]);
                mma8(acc[0][nt], af[0], bf0, bf1);
                mma8(acc[1][nt], af[1], bf0, bf1);
            }
        }
    }
    #pragma unroll
    for (int mt = 0; mt < 2; mt++) {
        int m = row0 + wm + mt*16 + g;
        #pragma unroll
        for (int nt = 0; nt < 8; nt++) {
            int n = col0 + wn + nt*8 + 2*tc;
            *(float2*)&C[m*H_ + n]     = make_float2(acc[mt][nt][0], acc[mt][nt][1]);
            *(float2*)&C[(m+8)*H_ + n] = make_float2(acc[mt][nt][2], acc[mt][nt][3]);
        }
    }
}

// ---------------- K5a: Hh/Ht = ent_emb @ W*_top (96x1024x768 x2, fp32) -------
__global__ void k_hx(const float* __restrict__ Wh, const float* __restrict__ Wt) {
    const int z = blockIdx.z;
    const float* W = z ? Wt : Wh;
    float* Cout = z ? g_Ht : g_Hh;
    const int row0 = blockIdx.y*32, col0 = blockIdx.x*128;
    __shared__ float As[16][32];
    __shared__ float Bs[16][128];
    float acc[2][8];
    #pragma unroll
    for (int i = 0; i < 2; i++)
        #pragma unroll
        for (int j = 0; j < 8; j++) acc[i][j] = 0.f;
    const int tid = threadIdx.x;
    const int tx = tid & 15, ty = tid >> 4;
    for (int kk = 0; kk < H_; kk += 16) {
        __syncthreads();
        if (tid < 128) {
            int m = tid >> 2, k4 = (tid & 3)*4;
            float4 av = *(const float4*)&g_entemb[(row0+m)*H_ + kk + k4];
            As[k4+0][m] = av.x; As[k4+1][m] = av.y;
            As[k4+2][m] = av.z; As[k4+3][m] = av.w;
        }
        #pragma unroll
        for (int q = 0; q < 2; q++) {
            int idx = q*256 + tid;
            int k = idx >> 5, n4 = (idx & 31)*4;
            *(float4*)&Bs[k][n4] = *(const float4*)&W[(kk+k)*EMB_ + col0 + n4];
        }
        __syncthreads();
        #pragma unroll
        for (int k = 0; k < 16; k++) {
            float a0 = As[k][ty*2], a1 = As[k][ty*2+1];
            float4 b0 = *(const float4*)&Bs[k][tx*8];
            float4 b1 = *(const float4*)&Bs[k][tx*8+4];
            float br[8] = {b0.x,b0.y,b0.z,b0.w,b1.x,b1.y,b1.z,b1.w};
            #pragma unroll
            for (int j = 0; j < 8; j++) {
                acc[0][j] += a0*br[j];
                acc[1][j] += a1*br[j];
            }
        }
    }
    #pragma unroll
    for (int i = 0; i < 2; i++) {
        int m = row0 + ty*2 + i;
        #pragma unroll
        for (int j = 0; j < 8; j += 4) {
            float4 v = make_float4(acc[i][j],acc[i][j+1],acc[i][j+2],acc[i][j+3]);
            *(float4*)&Cout[m*EMB_ + col0 + tx*8 + j] = v;
        }
    }
}

// ---------------- K5b: he/te = tanh(rel @ W*_bot + Hx + b) (tf32 mma) --------
__global__ void k_hete_mma(const float* __restrict__ Wh, const float* __restrict__ Wt,
                           const float* __restrict__ bh, const float* __restrict__ bt,
                           const int* __restrict__ hts) {
    const int col0 = blockIdx.x*128, row0 = blockIdx.y*128;
    const bool head = (col0 < EMB_);
    const float* W = head ? Wh : Wt;
    const int nb = head ? col0 : col0 - EMB_;
    __shared__ float As[16][132];
    __shared__ float Bs[16][132];
    const int tid = threadIdx.x;
    const int lane = tid & 31, wid = tid >> 5;
    const int g = lane >> 2, tc = lane & 3;
    const int wm = (wid >> 1)*32, wn = (wid & 1)*64;
    float acc[2][8][4];
    #pragma unroll
    for (int i = 0; i < 2; i++)
        #pragma unroll
        for (int j = 0; j < 8; j++)
            #pragma unroll
            for (int c = 0; c < 4; c++) acc[i][j][c] = 0.f;
    const int am = tid >> 1, ak = (tid & 1)*8;
    const int bk = tid >> 4, bn = (tid & 15)*8;
    for (int kk = 0; kk < H_; kk += 16) {
        float4 a0 = *(const float4*)&g_rel[(row0+am)*H_ + kk + ak];
        float4 a1 = *(const float4*)&g_rel[(row0+am)*H_ + kk + ak + 4];
        float4 b0 = *(const float4*)&W[(H_ + kk + bk)*EMB_ + nb + bn];
        float4 b1 = *(const float4*)&W[(H_ + kk + bk)*EMB_ + nb + bn + 4];
        __syncthreads();
        As[ak+0][am]=tf(a0.x); As[ak+1][am]=tf(a0.y);
        As[ak+2][am]=tf(a0.z); As[ak+3][am]=tf(a0.w);
        As[ak+4][am]=tf(a1.x); As[ak+5][am]=tf(a1.y);
        As[ak+6][am]=tf(a1.z); As[ak+7][am]=tf(a1.w);
        *(float4*)&Bs[bk][bn]   = make_float4(tf(b0.x),tf(b0.y),tf(b0.z),tf(b0.w));
        *(float4*)&Bs[bk][bn+4] = make_float4(tf(b1.x),tf(b1.y),tf(b1.z),tf(b1.w));
        __syncthreads();
        #pragma unroll
        for (int k8 = 0; k8 < 16; k8 += 8) {
            uint32_t af[2][4];
            #pragma unroll
            for (int mt = 0; mt < 2; mt++) {
                int mr = wm + mt*16 + g;
                af[mt][0] = FU(As[k8+tc][mr]);
                af[mt][1] = FU(As[k8+tc][mr+8]);
                af[mt][2] = FU(As[k8+tc+4][mr]);
                af[mt][3] = FU(As[k8+tc+4][mr+8]);
            }
            #pragma unroll
            for (int nt = 0; nt < 8; nt++) {
                int n = wn + nt*8 + g;
                uint32_t bf0 = FU(Bs[k8+tc][n]);
                uint32_t bf1 = FU(Bs[k8+tc+4][n]);
                mma8(acc[0][nt], af[0], bf0, bf1);
                mma8(acc[1][nt], af[1], bf0, bf1);
            }
        }
    }
    const float* Hx = head ? g_Hh : g_Ht;
    const float* bias = head ? bh : bt;
    float* outbuf = head ? g_he : g_te;
    #pragma unroll
    for (int mt = 0; mt < 2; mt++) {
        #pragma unroll
        for (int half = 0; half < 2; half++) {
            int m = row0 + wm + mt*16 + g + half*8;
            int b = m >> 9;
            int eidx = hts[m*2 + (head ? 0 : 1)];
            const float* hrow = Hx + (b*E_ + eidx)*EMB_;
            #pragma unroll
            for (int nt = 0; nt < 8; nt++) {
                int n = nb + wn + nt*8 + 2*tc;
                outbuf[m*EMB_ + n]   = tanhf(acc[mt][nt][2*half+0] + hrow[n]   + bias[n]);
                outbuf[m*EMB_ + n+1] = tanhf(acc[mt][nt][2*half+1] + hrow[n+1] + bias[n+1]);
            }
        }
    }
}

// ---------------- K6: Wbc = Wb @ Wc (49152x768x97, tf32 mma, N padded 128) ---
__global__ void k_wbc_mma(const float* __restrict__ Wb, const float* __restrict__ Wc) {
    const int row0 = blockIdx.x*128;
    __shared__ float As[16][132];
    __shared__ float Bs[16][132];
    const int tid = threadIdx.x;
    const int lane = tid & 31, wid = tid >> 5;
    const int g = lane >> 2, tc = lane & 3;
    const int wm = (wid >> 1)*32, wn = (wid & 1)*64;
    float acc[2][8][4];
    #pragma unroll
    for (int i = 0; i < 2; i++)
        #pragma unroll
        for (int j = 0; j < 8; j++)
            #pragma unroll
            for (int c = 0; c < 4; c++) acc[i][j][c] = 0.f;
    const int am = tid >> 1, ak = (tid & 1)*8;
    const int bk = tid >> 4, bn = (tid & 15)*8;
    for (int kk = 0; kk < EMB_; kk += 16) {
        float4 a0 = *(const float4*)&Wb[(row0+am)*EMB_ + kk + ak];
        float4 a1 = *(const float4*)&Wb[(row0+am)*EMB_ + kk + ak + 4];
        float bv[8];
        #pragma unroll
        for (int q = 0; q < 8; q++) {
            int n = bn + q;
            bv[q] = (n < NCLS_) ? tf(Wc[(kk+bk)*NCLS_ + n]) : 0.f;
        }
        __syncthreads();
        As[ak+0][am]=tf(a0.x); As[ak+1][am]=tf(a0.y);
        As[ak+2][am]=tf(a0.z); As[ak+3][am]=tf(a0.w);
        As[ak+4][am]=tf(a1.x); As[ak+5][am]=tf(a1.y);
        As[ak+6][am]=tf(a1.z); As[ak+7][am]=tf(a1.w);
        #pragma unroll
        for (int q = 0; q < 8; q++) Bs[bk][bn+q] = bv[q];
        __syncthreads();
        #pragma unroll
        for (int k8 = 0; k8 < 16; k8 += 8) {
            uint32_t af[2][4];
            #pragma unroll
            for (int mt = 0; mt < 2; mt++) {
                int mr = wm + mt*16 + g;
                af[mt][0] = FU(As[k8+tc][mr]);
                af[mt][1] = FU(As[k8+tc][mr+8]);
                af[mt][2] = FU(As[k8+tc+4][mr]);
                af[mt][3] = FU(As[k8+tc+4][mr+8]);
            }
            #pragma unroll
            for (int nt = 0; nt < 8; nt++) {
                int n = wn + nt*8 + g;
                uint32_t bf0 = FU(Bs[k8+tc][n]);
                uint32_t bf1 = FU(Bs[k8+tc+4][n]);
                mma8(acc[0][nt], af[0], bf0, bf1);
                mma8(acc[1][nt], af[1], bf0, bf1);
            }
        }
    }
    #pragma unroll
    for (int mt = 0; mt < 2; mt++) {
        int m = row0 + wm + mt*16 + g;
        #pragma unroll
        for (int nt = 0; nt < 8; nt++) {
            int n = wn + nt*8 + 2*tc;
            *(float2*)&g_Wbc[m*WLD_ + n]     = make_float2(acc[mt][nt][0], acc[mt][nt][1]);
            *(float2*)&g_Wbc[(m+8)*WLD_ + n] = make_float2(acc[mt][nt][2], acc[mt][nt][3]);
        }
    }
}

// ---------------- K7: bilinear classifier via virtual-A tf32 GEMM ------------
// grid (kb=12, rowblock=16); block computes 128 rows x 128 cols over K=4096
// A[m][i*64+j] = he[m][kb*64+i] * te[m][kb*64+j]  (generated from smem)
#define BIL_SMEM ((64*132 + 128*65 + 64*132)*4)
__global__ void k_bilinear_mma() {
    extern __shared__ float sm[];
    float (*te_t)[132] = (float(*)[132])sm;                    // [j][m]
    float (*he_s)[65]  = (float(*)[65])(sm + 64*132);          // [m][i]
    float (*Bs)[132]   = (float(*)[132])(sm + 64*132 + 128*65);// [j][n]
    const int kb = blockIdx.x;
    const int row0 = blockIdx.y*128;
    const int tid = threadIdx.x;
    const int lane = tid & 31, wid = tid >> 5;
    const int g = lane >> 2, tc = lane & 3;
    const int wm = (wid >> 1)*32, wn = (wid & 1)*64;
    // load he/te tiles (128 x 64 each)
    #pragma unroll
    for (int q = 0; q < 8; q++) {
        int idx = q*256 + tid;
        int m = idx >> 4, c4 = (idx & 15)*4;
        float4 hv = *(const float4*)&g_he[(row0+m)*EMB_ + kb*64 + c4];
        float4 tv = *(const float4*)&g_te[(row0+m)*EMB_ + kb*64 + c4];
        he_s[m][c4+0]=tf(hv.x); he_s[m][c4+1]=tf(hv.y);
        he_s[m][c4+2]=tf(hv.z); he_s[m][c4+3]=tf(hv.w);
        te_t[c4+0][m]=tf(tv.x); te_t[c4+1][m]=tf(tv.y);
        te_t[c4+2][m]=tf(tv.z); te_t[c4+3][m]=tf(tv.w);
    }
    float acc[2][8][4];
    #pragma unroll
    for (int i = 0; i < 2; i++)
        #pragma unroll
        for (int j = 0; j < 8; j++)
            #pragma unroll
            for (int c = 0; c < 4; c++) acc[i][j][c] = 0.f;
    for (int i = 0; i < 64; i++) {
        __syncthreads();
        // stage 64x128 Wbc rows for this (kb, i)
        #pragma unroll
        for (int q = 0; q < 8; q++) {
            int idx = q*256 + tid;
            int j = idx >> 5, n4 = (idx & 31)*4;
            float4 wv = *(const float4*)&g_Wbc[(kb*4096 + i*64 + j)*WLD_ + n4];
            *(float4*)&Bs[j][n4] = make_float4(tf(wv.x),tf(wv.y),tf(wv.z),tf(wv.w));
        }
        __syncthreads();
        float h[2][2];
        #pragma unroll
        for (int mt = 0; mt < 2; mt++) {
            h[mt][0] = he_s[wm + mt*16 + g][i];
            h[mt][1] = he_s[wm + mt*16 + g + 8][i];
        }
        #pragma unroll
        for (int j8 = 0; j8 < 8; j8++) {
            uint32_t af[2][4];
            #pragma unroll
            for (int mt = 0; mt < 2; mt++) {
                int mr = wm + mt*16 + g;
                af[mt][0] = FU(tf(te_t[j8*8+tc][mr]     * h[mt][0]));
                af[mt][1] = FU(tf(te_t[j8*8+tc][mr+8]   * h[mt][1]));
                af[mt][2] = FU(tf(te_t[j8*8+tc+4][mr]   * h[mt][0]));
                af[mt][3] = FU(tf(te_t[j8*8+tc+4][mr+8] * h[mt][1]));
            }
            #pragma unroll
            for (int nt = 0; nt < 8; nt++) {
                int n = wn + nt*8 + g;
                uint32_t bf0 = FU(Bs[j8*8+tc][n]);
                uint32_t bf1 = FU(Bs[j8*8+tc+4][n]);
                mma8(acc[0][nt], af[0], bf0, bf1);
                mma8(acc[1][nt], af[1], bf0, bf1);
            }
        }
    }
    #pragma unroll
    for (int mt = 0; mt < 2; mt++) {
        int m = row0 + wm + mt*16 + g;
        #pragma unroll
        for (int nt = 0; nt < 8; nt++) {
            int n = wn + nt*8 + 2*tc;
            *(float2*)&g_part[(kb*BR_ + m)*WLD_ + n]     = make_float2(acc[mt][nt][0], acc[mt][nt][1]);
            *(float2*)&g_part[(kb*BR_ + m + 8)*WLD_ + n] = make_float2(acc[mt][nt][2], acc[mt][nt][3]);
        }
    }
}

// ---------------- K8: reduce partials + bbc ----------------------------------
__global__ void k_reduce(float* __restrict__ out) {
    int idx = blockIdx.x*256 + threadIdx.x;
    if (idx < BR_*NCLS_) {
        int r = idx / NCLS_, n = idx % NCLS_;
        float a = g_bbc[n];
        #pragma unroll
        for (int k = 0; k < KB_; k++) a += g_part[(k*BR_ + r)*WLD_ + n];
        out[idx] = a;
    }
}

// ---------------- launch -----------------------------------------------------
extern "C" void kernel_launch(void* const* d_in, const int* in_sizes, int n_in,
                              void* d_out, int out_size) {
    const float* seq    = (const float*)d_in[0];
    const float* ent    = (const float*)d_in[1];
    const float* attn   = (const float*)d_in[2];
    const int*   labels = (const int*)  d_in[3];
    const int*   hts    = (const int*)  d_in[4];
    const float* Wh     = (const float*)d_in[5];
    const float* bh     = (const float*)d_in[6];
    const float* Wt     = (const float*)d_in[7];
    const float* bt     = (const float*)d_in[8];
    const float* Wb     = (const float*)d_in[9];
    const float* bb     = (const float*)d_in[10];
    const float* Wc     = (const float*)d_in[11];
    const float* bc     = (const float*)d_in[12];
    float* out = (float*)d_out;

    cudaFuncSetAttribute(k_bilinear_mma,
                         cudaFuncAttributeMaxDynamicSharedMemorySize, BIL_SMEM);

    k_prep<<<1, 128>>>(labels);
    k_bbc<<<1, 128>>>(bb, Wc, bc);
    k_entemb<<<B_*E_, 128>>>(ent);
    k_entattn<<<dim3(B_*E_, NH_), 256>>>(attn);
    k_ht<<<BR_, 256>>>(hts);
    k_rel_mma<<<dim3(H_/128, R_/128, B_), 256>>>(seq);
    k_hx<<<dim3(EMB_/128, 3, 2), 256>>>(Wh, Wt);
    k_hete_mma<<<dim3(12, 16), 256>>>(Wh, Wt, bh, bt, hts);
    k_wbc_mma<<<WROWS_/128, 256>>>(Wb, Wc);
    k_bilinear_mma<<<dim3(KB_, 16), 256, BIL_SMEM>>>();
    k_reduce<<<(BR_*NCLS_ + 255)/256, 256>>>(out);
}

// round 8
// speedup vs baseline: 2.2794x; 1.1303x over previous
#include <cuda_runtime.h>
#include <math.h>
#include <stdint.h>

#define B_ 4
#define L_ 1024
#define H_ 1024
#define NH_ 16
#define M_ 64
#define E_ 24
#define R_ 512
#define EMB_ 768
#define NCLS_ 97
#define KB_ 12            // EMB / 64
#define BR_ 2048          // B*R
#define WROWS_ 49152      // EMB*64
#define WLD_ 128          // padded N stride for Wbc / partials

// ---------------- scratch (static device globals; no allocation) -------------
__device__ int   g_cnt[B_*E_];
__device__ int   g_mlist[B_*E_*M_];
__device__ float g_entemb[B_*E_*H_];
__device__ float g_entattn[B_*E_*NH_*L_];
__device__ float g_ht[B_*R_*L_];
__device__ float g_rel[B_*R_*H_];
__device__ float g_he[BR_*EMB_];
__device__ float g_te[BR_*EMB_];
__device__ float g_Hh[B_*E_*EMB_];
__device__ float g_Ht[B_*E_*EMB_];
__device__ float g_Wbc[WROWS_*WLD_];
__device__ float g_part[KB_*BR_*WLD_];
__device__ float g_bbc[NCLS_];

// ---------------- tf32 / async helpers ---------------------------------------
__device__ __forceinline__ float tf(float x) {
    float r;
    asm("cvt.rna.tf32.f32 %0, %1;" : "=f"(r) : "f"(x));
    return r;
}
__device__ __forceinline__ void mma8(float c[4], const uint32_t a[4],
                                     uint32_t b0, uint32_t b1) {
    asm volatile(
        "mma.sync.aligned.m16n8k8.row.col.f32.tf32.tf32.f32 "
        "{%0,%1,%2,%3}, {%4,%5,%6,%7}, {%8,%9}, {%0,%1,%2,%3};\n"
        : "+f"(c[0]), "+f"(c[1]), "+f"(c[2]), "+f"(c[3])
        : "r"(a[0]), "r"(a[1]), "r"(a[2]), "r"(a[3]), "r"(b0), "r"(b1));
}
__device__ __forceinline__ void cpa16(uint32_t dst, const float* src) {
    asm volatile("cp.async.cg.shared.global [%0], [%1], 16;\n"
                 :: "r"(dst), "l"(src));
}
#define FU(x) __float_as_uint(x)

// ---------------- K0: mention lists per (b,e) --------------------------------
__global__ void k_prep(const int* __restrict__ labels) {
    int t = threadIdx.x;
    if (t < B_*E_) {
        int b = t / E_, e = t % E_;
        int c = 0;
        for (int m = 0; m < M_; m++)
            if (labels[b*M_ + m] == e) g_mlist[t*M_ + c++] = m;
        g_cnt[t] = c;
    }
}

// ---------------- bbc = bb @ Wc + bc ----------------------------------------
__global__ void k_bbc(const float* __restrict__ bb, const float* __restrict__ Wc,
                      const float* __restrict__ bc) {
    int n = threadIdx.x;
    if (n < NCLS_) {
        float a = bc[n];
        for (int d = 0; d < EMB_; d++) a += bb[d] * Wc[d*NCLS_ + n];
        g_bbc[n] = a;
    }
}

// ---------------- K1: entity logsumexp pooling -------------------------------
__global__ void k_entemb(const float* __restrict__ ent) {
    int be = blockIdx.x;
    int b = be / E_;
    __shared__ int lst[M_];
    __shared__ int scnt;
    if (threadIdx.x == 0) scnt = g_cnt[be];
    __syncthreads();
    int cnt = scnt;
    if (threadIdx.x < cnt) lst[threadIdx.x] = g_mlist[be*M_ + threadIdx.x];
    __syncthreads();
    for (int h = threadIdx.x; h < H_; h += blockDim.x) {
        float o = 0.f;
        if (cnt > 0) {
            float mx = -3.4e38f;
            for (int c = 0; c < cnt; c++)
                mx = fmaxf(mx, ent[(b*M_ + lst[c])*H_ + h]);
            float s = 0.f;
            for (int c = 0; c < cnt; c++)
                s += expf(ent[(b*M_ + lst[c])*H_ + h] - mx);
            o = mx + logf(s);
        }
        g_entemb[be*H_ + h] = o;
    }
}

// ---------------- K2: entity->seq attention (mean over mentions) -------------
__global__ void k_entattn(const float* __restrict__ attn) {
    int be = blockIdx.x, nh = blockIdx.y;
    int b = be / E_;
    __shared__ int lst[M_];
    __shared__ int scnt;
    if (threadIdx.x == 0) scnt = g_cnt[be];
    __syncthreads();
    int cnt = scnt;
    if (threadIdx.x < cnt) lst[threadIdx.x] = g_mlist[be*M_ + threadIdx.x];
    __syncthreads();
    float inv = 1.f / (float)(cnt > 1 ? cnt : 1);
    const float* base = attn + (b*NH_ + nh)*M_*L_;
    float* outp = g_entattn + (be*NH_ + nh)*L_;
    for (int l = threadIdx.x; l < L_; l += blockDim.x) {
        float a = 0.f;
        for (int c = 0; c < cnt; c++) a += base[lst[c]*L_ + l];
        outp[l] = a * inv;
    }
}

// ---------------- K3: pair attention product + normalize ---------------------
__global__ void k_ht(const int* __restrict__ hts) {
    int br = blockIdx.x;
    int b = br >> 9;
    int h = hts[br*2 + 0], t = hts[br*2 + 1];
    const float* ph = g_entattn + (b*E_ + h)*NH_*L_;
    const float* pt = g_entattn + (b*E_ + t)*NH_*L_;
    float v[4];
    float lsum = 0.f;
    #pragma unroll
    for (int q = 0; q < 4; q++) {
        int l = threadIdx.x + q*256;
        float s = 0.f;
        #pragma unroll
        for (int nh = 0; nh < NH_; nh++)
            s += ph[nh*L_ + l] * pt[nh*L_ + l];
        v[q] = s * (1.f/NH_);
        lsum += v[q];
    }
    __shared__ float red[256];
    red[threadIdx.x] = lsum;
    __syncthreads();
    for (int s = 128; s > 0; s >>= 1) {
        if (threadIdx.x < s) red[threadIdx.x] += red[threadIdx.x + s];
        __syncthreads();
    }
    float inv = 1.f / (red[0] + 1e-5f);
    #pragma unroll
    for (int q = 0; q < 4; q++) {
        int l = threadIdx.x + q*256;
        g_ht[br*L_ + l] = v[q] * inv;
    }
}

// ---------------- K4: rel = ht @ seq (tf32 mma, reg-prefetch pipelined) ------
__global__ void k_rel_mma(const float* __restrict__ seq) {
    const int b = blockIdx.z;
    const float* A = g_ht + b*R_*L_;
    const float* Bm = seq + b*L_*H_;
    float* C = g_rel + b*R_*H_;
    const int row0 = blockIdx.y*128, col0 = blockIdx.x*128;
    __shared__ float As[16][132];
    __shared__ float Bs[16][132];
    const int tid = threadIdx.x;
    const int lane = tid & 31, wid = tid >> 5;
    const int g = lane >> 2, tc = lane & 3;
    const int wm = (wid >> 1)*32, wn = (wid & 1)*64;
    float acc[2][8][4];
    #pragma unroll
    for (int i = 0; i < 2; i++)
        #pragma unroll
        for (int j = 0; j < 8; j++)
            #pragma unroll
            for (int c = 0; c < 4; c++) acc[i][j][c] = 0.f;
    const int am = tid >> 1, ak = (tid & 1)*8;
    const int bk = tid >> 4, bn = (tid & 15)*8;
    float4 a0 = *(const float4*)&A[(row0+am)*L_ + ak];
    float4 a1 = *(const float4*)&A[(row0+am)*L_ + ak + 4];
    float4 b0 = *(const float4*)&Bm[bk*H_ + col0 + bn];
    float4 b1 = *(const float4*)&Bm[bk*H_ + col0 + bn + 4];
    for (int kk = 0; kk < L_; kk += 16) {
        __syncthreads();
        As[ak+0][am]=tf(a0.x); As[ak+1][am]=tf(a0.y);
        As[ak+2][am]=tf(a0.z); As[ak+3][am]=tf(a0.w);
        As[ak+4][am]=tf(a1.x); As[ak+5][am]=tf(a1.y);
        As[ak+6][am]=tf(a1.z); As[ak+7][am]=tf(a1.w);
        *(float4*)&Bs[bk][bn]   = make_float4(tf(b0.x),tf(b0.y),tf(b0.z),tf(b0.w));
        *(float4*)&Bs[bk][bn+4] = make_float4(tf(b1.x),tf(b1.y),tf(b1.z),tf(b1.w));
        __syncthreads();
        if (kk + 16 < L_) {
            a0 = *(const float4*)&A[(row0+am)*L_ + kk+16 + ak];
            a1 = *(const float4*)&A[(row0+am)*L_ + kk+16 + ak + 4];
            b0 = *(const float4*)&Bm[(kk+16+bk)*H_ + col0 + bn];
            b1 = *(const float4*)&Bm[(kk+16+bk)*H_ + col0 + bn + 4];
        }
        #pragma unroll
        for (int k8 = 0; k8 < 16; k8 += 8) {
            uint32_t af[2][4];
            #pragma unroll
            for (int mt = 0; mt < 2; mt++) {
                int mr = wm + mt*16 + g;
                af[mt][0] = FU(As[k8+tc][mr]);
                af[mt][1] = FU(As[k8+tc][mr+8]);
                af[mt][2] = FU(As[k8+tc+4][mr]);
                af[mt][3] = FU(As[k8+tc+4][mr+8]);
            }
            #pragma unroll
            for (int nt = 0; nt < 8; nt++) {
                int n = wn + nt*8 + g;
                uint32_t bf0 = FU(Bs[k8+tc][n]);
                uint32_t bf1 = FU(Bs[k8+tc+4][n]);
                mma8(acc[0][nt], af[0], bf0, bf1);
                mma8(acc[1][nt], af[1], bf0, bf1);
            }
        }
    }
    #pragma unroll
    for (int mt = 0; mt < 2; mt++) {
        int m = row0 + wm + mt*16 + g;
        #pragma unroll
        for (int nt = 0; nt < 8; nt++) {
            int n = col0 + wn + nt*8 + 2*tc;
            *(float2*)&C[m*H_ + n]     = make_float2(acc[mt][nt][0], acc[mt][nt][1]);
            *(float2*)&C[(m+8)*H_ + n] = make_float2(acc[mt][nt][2], acc[mt][nt][3]);
        }
    }
}

// ---------------- K5a: Hh/Ht = ent_emb @ W*_top (96x1024x768 x2, fp32) -------
__global__ void k_hx(const float* __restrict__ Wh, const float* __restrict__ Wt) {
    const int z = blockIdx.z;
    const float* W = z ? Wt : Wh;
    float* Cout = z ? g_Ht : g_Hh;
    const int row0 = blockIdx.y*32, col0 = blockIdx.x*128;
    __shared__ float As[16][32];
    __shared__ float Bs[16][128];
    float acc[2][8];
    #pragma unroll
    for (int i = 0; i < 2; i++)
        #pragma unroll
        for (int j = 0; j < 8; j++) acc[i][j] = 0.f;
    const int tid = threadIdx.x;
    const int tx = tid & 15, ty = tid >> 4;
    for (int kk = 0; kk < H_; kk += 16) {
        __syncthreads();
        if (tid < 128) {
            int m = tid >> 2, k4 = (tid & 3)*4;
            float4 av = *(const float4*)&g_entemb[(row0+m)*H_ + kk + k4];
            As[k4+0][m] = av.x; As[k4+1][m] = av.y;
            As[k4+2][m] = av.z; As[k4+3][m] = av.w;
        }
        #pragma unroll
        for (int q = 0; q < 2; q++) {
            int idx = q*256 + tid;
            int k = idx >> 5, n4 = (idx & 31)*4;
            *(float4*)&Bs[k][n4] = *(const float4*)&W[(kk+k)*EMB_ + col0 + n4];
        }
        __syncthreads();
        #pragma unroll
        for (int k = 0; k < 16; k++) {
            float a0 = As[k][ty*2], a1 = As[k][ty*2+1];
            float4 b0 = *(const float4*)&Bs[k][tx*8];
            float4 b1 = *(const float4*)&Bs[k][tx*8+4];
            float br[8] = {b0.x,b0.y,b0.z,b0.w,b1.x,b1.y,b1.z,b1.w};
            #pragma unroll
            for (int j = 0; j < 8; j++) {
                acc[0][j] += a0*br[j];
                acc[1][j] += a1*br[j];
            }
        }
    }
    #pragma unroll
    for (int i = 0; i < 2; i++) {
        int m = row0 + ty*2 + i;
        #pragma unroll
        for (int j = 0; j < 8; j += 4) {
            float4 v = make_float4(acc[i][j],acc[i][j+1],acc[i][j+2],acc[i][j+3]);
            *(float4*)&Cout[m*EMB_ + col0 + tx*8 + j] = v;
        }
    }
}

// ---------------- K5b: he/te = tanh(rel @ W*_bot + Hx + b), tf32-rounded out -
__global__ void k_hete_mma(const float* __restrict__ Wh, const float* __restrict__ Wt,
                           const float* __restrict__ bh, const float* __restrict__ bt,
                           const int* __restrict__ hts) {
    const int col0 = blockIdx.x*128, row0 = blockIdx.y*128;
    const bool head = (col0 < EMB_);
    const float* W = head ? Wh : Wt;
    const int nb = head ? col0 : col0 - EMB_;
    __shared__ float As[16][132];
    __shared__ float Bs[16][132];
    const int tid = threadIdx.x;
    const int lane = tid & 31, wid = tid >> 5;
    const int g = lane >> 2, tc = lane & 3;
    const int wm = (wid >> 1)*32, wn = (wid & 1)*64;
    float acc[2][8][4];
    #pragma unroll
    for (int i = 0; i < 2; i++)
        #pragma unroll
        for (int j = 0; j < 8; j++)
            #pragma unroll
            for (int c = 0; c < 4; c++) acc[i][j][c] = 0.f;
    const int am = tid >> 1, ak = (tid & 1)*8;
    const int bk = tid >> 4, bn = (tid & 15)*8;
    float4 a0 = *(const float4*)&g_rel[(row0+am)*H_ + ak];
    float4 a1 = *(const float4*)&g_rel[(row0+am)*H_ + ak + 4];
    float4 b0 = *(const float4*)&W[(H_ + bk)*EMB_ + nb + bn];
    float4 b1 = *(const float4*)&W[(H_ + bk)*EMB_ + nb + bn + 4];
    for (int kk = 0; kk < H_; kk += 16) {
        __syncthreads();
        As[ak+0][am]=tf(a0.x); As[ak+1][am]=tf(a0.y);
        As[ak+2][am]=tf(a0.z); As[ak+3][am]=tf(a0.w);
        As[ak+4][am]=tf(a1.x); As[ak+5][am]=tf(a1.y);
        As[ak+6][am]=tf(a1.z); As[ak+7][am]=tf(a1.w);
        *(float4*)&Bs[bk][bn]   = make_float4(tf(b0.x),tf(b0.y),tf(b0.z),tf(b0.w));
        *(float4*)&Bs[bk][bn+4] = make_float4(tf(b1.x),tf(b1.y),tf(b1.z),tf(b1.w));
        __syncthreads();
        if (kk + 16 < H_) {
            a0 = *(const float4*)&g_rel[(row0+am)*H_ + kk+16 + ak];
            a1 = *(const float4*)&g_rel[(row0+am)*H_ + kk+16 + ak + 4];
            b0 = *(const float4*)&W[(H_ + kk+16 + bk)*EMB_ + nb + bn];
            b1 = *(const float4*)&W[(H_ + kk+16 + bk)*EMB_ + nb + bn + 4];
        }
        #pragma unroll
        for (int k8 = 0; k8 < 16; k8 += 8) {
            uint32_t af[2][4];
            #pragma unroll
            for (int mt = 0; mt < 2; mt++) {
                int mr = wm + mt*16 + g;
                af[mt][0] = FU(As[k8+tc][mr]);
                af[mt][1] = FU(As[k8+tc][mr+8]);
                af[mt][2] = FU(As[k8+tc+4][mr]);
                af[mt][3] = FU(As[k8+tc+4][mr+8]);
            }
            #pragma unroll
            for (int nt = 0; nt < 8; nt++) {
                int n = wn + nt*8 + g;
                uint32_t bf0 = FU(Bs[k8+tc][n]);
                uint32_t bf1 = FU(Bs[k8+tc+4][n]);
                mma8(acc[0][nt], af[0], bf0, bf1);
                mma8(acc[1][nt], af[1], bf0, bf1);
            }
        }
    }
    const float* Hx = head ? g_Hh : g_Ht;
    const float* bias = head ? bh : bt;
    float* outbuf = head ? g_he : g_te;
    #pragma unroll
    for (int mt = 0; mt < 2; mt++) {
        #pragma unroll
        for (int half = 0; half < 2; half++) {
            int m = row0 + wm + mt*16 + g + half*8;
            int b = m >> 9;
            int eidx = hts[m*2 + (head ? 0 : 1)];
            const float* hrow = Hx + (b*E_ + eidx)*EMB_;
            #pragma unroll
            for (int nt = 0; nt < 8; nt++) {
                int n = nb + wn + nt*8 + 2*tc;
                outbuf[m*EMB_ + n]   = tf(tanhf(acc[mt][nt][2*half+0] + hrow[n]   + bias[n]));
                outbuf[m*EMB_ + n+1] = tf(tanhf(acc[mt][nt][2*half+1] + hrow[n+1] + bias[n+1]));
            }
        }
    }
}

// ---------------- K6: Wbc = Wb @ Wc (tf32 mma, tf32-rounded output) ----------
__global__ void k_wbc_mma(const float* __restrict__ Wb, const float* __restrict__ Wc) {
    const int row0 = blockIdx.x*128;
    __shared__ float As[16][132];
    __shared__ float Bs[16][132];
    const int tid = threadIdx.x;
    const int lane = tid & 31, wid = tid >> 5;
    const int g = lane >> 2, tc = lane & 3;
    const int wm = (wid >> 1)*32, wn = (wid & 1)*64;
    float acc[2][8][4];
    #pragma unroll
    for (int i = 0; i < 2; i++)
        #pragma unroll
        for (int j = 0; j < 8; j++)
            #pragma unroll
            for (int c = 0; c < 4; c++) acc[i][j][c] = 0.f;
    const int am = tid >> 1, ak = (tid & 1)*8;
    const int bk = tid >> 4, bn = (tid & 15)*8;
    float4 a0 = *(const float4*)&Wb[(row0+am)*EMB_ + ak];
    float4 a1 = *(const float4*)&Wb[(row0+am)*EMB_ + ak + 4];
    float bv[8];
    #pragma unroll
    for (int q = 0; q < 8; q++) {
        int n = bn + q;
        bv[q] = (n < NCLS_) ? Wc[bk*NCLS_ + n] : 0.f;
    }
    for (int kk = 0; kk < EMB_; kk += 16) {
        __syncthreads();
        As[ak+0][am]=tf(a0.x); As[ak+1][am]=tf(a0.y);
        As[ak+2][am]=tf(a0.z); As[ak+3][am]=tf(a0.w);
        As[ak+4][am]=tf(a1.x); As[ak+5][am]=tf(a1.y);
        As[ak+6][am]=tf(a1.z); As[ak+7][am]=tf(a1.w);
        #pragma unroll
        for (int q = 0; q < 8; q++) Bs[bk][bn+q] = tf(bv[q]);
        __syncthreads();
        if (kk + 16 < EMB_) {
            a0 = *(const float4*)&Wb[(row0+am)*EMB_ + kk+16 + ak];
            a1 = *(const float4*)&Wb[(row0+am)*EMB_ + kk+16 + ak + 4];
            #pragma unroll
            for (int q = 0; q < 8; q++) {
                int n = bn + q;
                bv[q] = (n < NCLS_) ? Wc[(kk+16+bk)*NCLS_ + n] : 0.f;
            }
        }
        #pragma unroll
        for (int k8 = 0; k8 < 16; k8 += 8) {
            uint32_t af[2][4];
            #pragma unroll
            for (int mt = 0; mt < 2; mt++) {
                int mr = wm + mt*16 + g;
                af[mt][0] = FU(As[k8+tc][mr]);
                af[mt][1] = FU(As[k8+tc][mr+8]);
                af[mt][2] = FU(As[k8+tc+4][mr]);
                af[mt][3] = FU(As[k8+tc+4][mr+8]);
            }
            #pragma unroll
            for (int nt = 0; nt < 8; nt++) {
                int n = wn + nt*8 + g;
                uint32_t bf0 = FU(Bs[k8+tc][n]);
                uint32_t bf1 = FU(Bs[k8+tc+4][n]);
                mma8(acc[0][nt], af[0], bf0, bf1);
                mma8(acc[1][nt], af[1], bf0, bf1);
            }
        }
    }
    #pragma unroll
    for (int mt = 0; mt < 2; mt++) {
        int m = row0 + wm + mt*16 + g;
        #pragma unroll
        for (int nt = 0; nt < 8; nt++) {
            int n = wn + nt*8 + 2*tc;
            *(float2*)&g_Wbc[m*WLD_ + n]     = make_float2(tf(acc[mt][nt][0]), tf(acc[mt][nt][1]));
            *(float2*)&g_Wbc[(m+8)*WLD_ + n] = make_float2(tf(acc[mt][nt][2]), tf(acc[mt][nt][3]));
        }
    }
}

// ---------------- K7: bilinear via virtual-A tf32 GEMM, cp.async pipelined ---
// smem: Bs[2][64][136] | te_t[64][136] | he_s[128][68]   (68-stride: 16B-aligned rows)
#define BIL_SMEM ((3*64*136 + 128*68)*4)
__global__ void k_bilinear_mma() {
    extern __shared__ float sm[];
    float (*Bs0)[136] = (float(*)[136])sm;
    float (*Bs1)[136] = (float(*)[136])(sm + 64*136);
    float (*te_t)[136] = (float(*)[136])(sm + 2*64*136);
    float (*he_s)[68]  = (float(*)[68])(sm + 3*64*136);
    const uint32_t sm_u32 = (uint32_t)__cvta_generic_to_shared(sm);
    const int kb = blockIdx.x;
    const int row0 = blockIdx.y*128;
    const int tid = threadIdx.x;
    const int lane = tid & 31, wid = tid >> 5;
    const int g = lane >> 2, tc = lane & 3;
    const int wm = (wid >> 1)*32, wn = (wid & 1)*64;
    // load he/te tiles (pre-rounded to tf32 by k_hete)
    #pragma unroll
    for (int q = 0; q < 8; q++) {
        int idx = q*256 + tid;
        int m = idx >> 4, c4 = (idx & 15)*4;
        float4 hv = *(const float4*)&g_he[(row0+m)*EMB_ + kb*64 + c4];
        float4 tv = *(const float4*)&g_te[(row0+m)*EMB_ + kb*64 + c4];
        *(float4*)&he_s[m][c4] = hv;      // stride 68 floats = 272B, 16B-aligned
        te_t[c4+0][m]=tv.x; te_t[c4+1][m]=tv.y;
        te_t[c4+2][m]=tv.z; te_t[c4+3][m]=tv.w;
    }
    // prologue: stage i=0 into buffer 0
    {
        const float* src = g_Wbc + (kb*4096)*WLD_;
        #pragma unroll
        for (int q = 0; q < 8; q++) {
            int c = q*256 + tid;
            int j = c >> 5, nc = (c & 31)*4;
            cpa16(sm_u32 + (j*136 + nc)*4, src + j*WLD_ + nc);
        }
        asm volatile("cp.async.commit_group;\n");
    }
    float acc[2][8][4];
    #pragma unroll
    for (int i = 0; i < 2; i++)
        #pragma unroll
        for (int j = 0; j < 8; j++)
            #pragma unroll
            for (int c = 0; c < 4; c++) acc[i][j][c] = 0.f;
    for (int i = 0; i < 64; i++) {
        if (i + 1 < 64) {
            const float* src = g_Wbc + (kb*4096 + (i+1)*64)*WLD_;
            const uint32_t dstb = sm_u32 + ((i+1)&1)*64*136*4;
            #pragma unroll
            for (int q = 0; q < 8; q++) {
                int c = q*256 + tid;
                int j = c >> 5, nc = (c & 31)*4;
                cpa16(dstb + (j*136 + nc)*4, src + j*WLD_ + nc);
            }
            asm volatile("cp.async.commit_group;\n");
            asm volatile("cp.async.wait_group 1;\n");
        } else {
            asm volatile("cp.async.wait_group 0;\n");
        }
        __syncthreads();
        float (*Bsb)[136] = (i & 1) ? Bs1 : Bs0;
        float h[2][2];
        #pragma unroll
        for (int mt = 0; mt < 2; mt++) {
            h[mt][0] = he_s[wm + mt*16 + g][i];
            h[mt][1] = he_s[wm + mt*16 + g + 8][i];
        }
        #pragma unroll
        for (int j8 = 0; j8 < 8; j8++) {
            uint32_t af[2][4];
            #pragma unroll
            for (int mt = 0; mt < 2; mt++) {
                int mr = wm + mt*16 + g;
                af[mt][0] = FU(te_t[j8*8+tc][mr]     * h[mt][0]);
                af[mt][1] = FU(te_t[j8*8+tc][mr+8]   * h[mt][1]);
                af[mt][2] = FU(te_t[j8*8+tc+4][mr]   * h[mt][0]);
                af[mt][3] = FU(te_t[j8*8+tc+4][mr+8] * h[mt][1]);
            }
            #pragma unroll
            for (int nt = 0; nt < 8; nt++) {
                int n = wn + nt*8 + g;
                uint32_t bf0 = FU(Bsb[j8*8+tc][n]);
                uint32_t bf1 = FU(Bsb[j8*8+tc+4][n]);
                mma8(acc[0][nt], af[0], bf0, bf1);
                mma8(acc[1][nt], af[1], bf0, bf1);
            }
        }
        __syncthreads();
    }
    #pragma unroll
    for (int mt = 0; mt < 2; mt++) {
        int m = row0 + wm + mt*16 + g;
        #pragma unroll
        for (int nt = 0; nt < 8; nt++) {
            int n = wn + nt*8 + 2*tc;
            *(float2*)&g_part[(kb*BR_ + m)*WLD_ + n]     = make_float2(acc[mt][nt][0], acc[mt][nt][1]);
            *(float2*)&g_part[(kb*BR_ + m + 8)*WLD_ + n] = make_float2(acc[mt][nt][2], acc[mt][nt][3]);
        }
    }
}

// ---------------- K8: reduce partials + bbc ----------------------------------
__global__ void k_reduce(float* __restrict__ out) {
    int idx = blockIdx.x*256 + threadIdx.x;
    if (idx < BR_*NCLS_) {
        int r = idx / NCLS_, n = idx % NCLS_;
        float a = g_bbc[n];
        #pragma unroll
        for (int k = 0; k < KB_; k++) a += g_part[(k*BR_ + r)*WLD_ + n];
        out[idx] = a;
    }
}

// ---------------- launch -----------------------------------------------------
extern "C" void kernel_launch(void* const* d_in, const int* in_sizes, int n_in,
                              void* d_out, int out_size) {
    const float* seq    = (const float*)d_in[0];
    const float* ent    = (const float*)d_in[1];
    const float* attn   = (const float*)d_in[2];
    const int*   labels = (const int*)  d_in[3];
    const int*   hts    = (const int*)  d_in[4];
    const float* Wh     = (const float*)d_in[5];
    const float* bh     = (const float*)d_in[6];
    const float* Wt     = (const float*)d_in[7];
    const float* bt     = (const float*)d_in[8];
    const float* Wb     = (const float*)d_in[9];
    const float* bb     = (const float*)d_in[10];
    const float* Wc     = (const float*)d_in[11];
    const float* bc     = (const float*)d_in[12];
    float* out = (float*)d_out;

    cudaFuncSetAttribute(k_bilinear_mma,
                         cudaFuncAttributeMaxDynamicSharedMemorySize, BIL_SMEM);

    k_prep<<<1, 128>>>(labels);
    k_bbc<<<1, 128>>>(bb, Wc, bc);
    k_entemb<<<B_*E_, 128>>>(ent);
    k_entattn<<<dim3(B_*E_, NH_), 256>>>(attn);
    k_ht<<<BR_, 256>>>(hts);
    k_rel_mma<<<dim3(H_/128, R_/128, B_), 256>>>(seq);
    k_hx<<<dim3(EMB_/128, 3, 2), 256>>>(Wh, Wt);
    k_hete_mma<<<dim3(12, 16), 256>>>(Wh, Wt, bh, bt, hts);
    k_wbc_mma<<<WROWS_/128, 256>>>(Wb, Wc);
    k_bilinear_mma<<<dim3(KB_, 16), 256, BIL_SMEM>>>();
    k_reduce<<<(BR_*NCLS_ + 255)/256, 256>>>(out);
}

// round 9
// speedup vs baseline: 3.1478x; 1.3810x over previous
#include <cuda_runtime.h>
#include <math.h>
#include <stdint.h>

#define B_ 4
#define L_ 1024
#define H_ 1024
#define NH_ 16
#define M_ 64
#define E_ 24
#define R_ 512
#define EMB_ 768
#define NCLS_ 97
#define KB_ 12            // EMB / 64
#define BR_ 2048          // B*R
#define WROWS_ 49152      // EMB*64
#define WLD_ 128          // padded N stride for Wbc / partials

// ---------------- scratch (static device globals; no allocation) -------------
__device__ int      g_cnt[B_*E_];
__device__ int      g_mlist[B_*E_*M_];
__device__ float    g_entemb[B_*E_*H_];
__device__ float    g_entattn[B_*E_*NH_*L_];
__device__ float    g_ht[B_*R_*L_];
__device__ float    g_rel[B_*R_*H_];
__device__ float    g_he[BR_*EMB_];
__device__ float    g_te[BR_*EMB_];
__device__ float    g_Hh[B_*E_*EMB_];
__device__ float    g_Ht[B_*E_*EMB_];
__device__ float    g_Wbc[WROWS_*WLD_];
__device__ uint32_t g_WbcH[(WROWS_/2)*WLD_];   // half2-packed over row pairs
__device__ float    g_part[KB_*BR_*WLD_];
__device__ float    g_bbc[NCLS_];

// ---------------- fp16 / async helpers ---------------------------------------
__device__ __forceinline__ uint32_t pk(float lo, float hi) {
    uint32_t r;
    asm("cvt.rn.f16x2.f32 %0, %1, %2;" : "=r"(r) : "f"(hi), "f"(lo));
    return r;
}
__device__ __forceinline__ uint32_t mul2(uint32_t a, uint32_t b) {
    uint32_t r;
    asm("mul.rn.f16x2 %0, %1, %2;" : "=r"(r) : "r"(a), "r"(b));
    return r;
}
__device__ __forceinline__ void mma16(float c[4], const uint32_t a[4],
                                      uint32_t b0, uint32_t b1) {
    asm volatile(
        "mma.sync.aligned.m16n8k16.row.col.f32.f16.f16.f32 "
        "{%0,%1,%2,%3}, {%4,%5,%6,%7}, {%8,%9}, {%0,%1,%2,%3};\n"
        : "+f"(c[0]), "+f"(c[1]), "+f"(c[2]), "+f"(c[3])
        : "r"(a[0]), "r"(a[1]), "r"(a[2]), "r"(a[3]), "r"(b0), "r"(b1));
}
__device__ __forceinline__ void cpa16(uint32_t dst, const void* src) {
    asm volatile("cp.async.cg.shared.global [%0], [%1], 16;\n"
                 :: "r"(dst), "l"(src));
}

// ---------------- K0: mention lists per (b,e) --------------------------------
__global__ void k_prep(const int* __restrict__ labels) {
    int t = threadIdx.x;
    if (t < B_*E_) {
        int b = t / E_, e = t % E_;
        int c = 0;
        for (int m = 0; m < M_; m++)
            if (labels[b*M_ + m] == e) g_mlist[t*M_ + c++] = m;
        g_cnt[t] = c;
    }
}

// ---------------- bbc = bb @ Wc + bc ----------------------------------------
__global__ void k_bbc(const float* __restrict__ bb, const float* __restrict__ Wc,
                      const float* __restrict__ bc) {
    int n = threadIdx.x;
    if (n < NCLS_) {
        float a = bc[n];
        for (int d = 0; d < EMB_; d++) a += bb[d] * Wc[d*NCLS_ + n];
        g_bbc[n] = a;
    }
}

// ---------------- K1: entity logsumexp pooling -------------------------------
__global__ void k_entemb(const float* __restrict__ ent) {
    int be = blockIdx.x;
    int b = be / E_;
    __shared__ int lst[M_];
    __shared__ int scnt;
    if (threadIdx.x == 0) scnt = g_cnt[be];
    __syncthreads();
    int cnt = scnt;
    if (threadIdx.x < cnt) lst[threadIdx.x] = g_mlist[be*M_ + threadIdx.x];
    __syncthreads();
    for (int h = threadIdx.x; h < H_; h += blockDim.x) {
        float o = 0.f;
        if (cnt > 0) {
            float mx = -3.4e38f;
            for (int c = 0; c < cnt; c++)
                mx = fmaxf(mx, ent[(b*M_ + lst[c])*H_ + h]);
            float s = 0.f;
            for (int c = 0; c < cnt; c++)
                s += expf(ent[(b*M_ + lst[c])*H_ + h] - mx);
            o = mx + logf(s);
        }
        g_entemb[be*H_ + h] = o;
    }
}

// ---------------- K2: entity->seq attention (mean over mentions) -------------
__global__ void k_entattn(const float* __restrict__ attn) {
    int be = blockIdx.x, nh = blockIdx.y;
    int b = be / E_;
    __shared__ int lst[M_];
    __shared__ int scnt;
    if (threadIdx.x == 0) scnt = g_cnt[be];
    __syncthreads();
    int cnt = scnt;
    if (threadIdx.x < cnt) lst[threadIdx.x] = g_mlist[be*M_ + threadIdx.x];
    __syncthreads();
    float inv = 1.f / (float)(cnt > 1 ? cnt : 1);
    const float* base = attn + (b*NH_ + nh)*M_*L_;
    float* outp = g_entattn + (be*NH_ + nh)*L_;
    for (int l = threadIdx.x; l < L_; l += blockDim.x) {
        float a = 0.f;
        for (int c = 0; c < cnt; c++) a += base[lst[c]*L_ + l];
        outp[l] = a * inv;
    }
}

// ---------------- K3: pair attention product + normalize ---------------------
__global__ void k_ht(const int* __restrict__ hts) {
    int br = blockIdx.x;
    int b = br >> 9;
    int h = hts[br*2 + 0], t = hts[br*2 + 1];
    const float* ph = g_entattn + (b*E_ + h)*NH_*L_;
    const float* pt = g_entattn + (b*E_ + t)*NH_*L_;
    float v[4];
    float lsum = 0.f;
    #pragma unroll
    for (int q = 0; q < 4; q++) {
        int l = threadIdx.x + q*256;
        float s = 0.f;
        #pragma unroll
        for (int nh = 0; nh < NH_; nh++)
            s += ph[nh*L_ + l] * pt[nh*L_ + l];
        v[q] = s * (1.f/NH_);
        lsum += v[q];
    }
    __shared__ float red[256];
    red[threadIdx.x] = lsum;
    __syncthreads();
    for (int s = 128; s > 0; s >>= 1) {
        if (threadIdx.x < s) red[threadIdx.x] += red[threadIdx.x + s];
        __syncthreads();
    }
    float inv = 1.f / (red[0] + 1e-5f);
    #pragma unroll
    for (int q = 0; q < 4; q++) {
        int l = threadIdx.x + q*256;
        g_ht[br*L_ + l] = v[q] * inv;
    }
}

// ---------------- K4: rel = ht @ seq (fp16 mma, reg-prefetch pipelined) ------
__global__ void k_rel_mma(const float* __restrict__ seq) {
    const int b = blockIdx.z;
    const float* A = g_ht + b*R_*L_;
    const float* Bm = seq + b*L_*H_;
    float* C = g_rel + b*R_*H_;
    const int row0 = blockIdx.y*128, col0 = blockIdx.x*128;
    __shared__ uint32_t As32[8][136];
    __shared__ uint32_t Bs32[8][136];
    const int tid = threadIdx.x;
    const int lane = tid & 31, wid = tid >> 5;
    const int g = lane >> 2, tc = lane & 3;
    const int wm = (wid >> 1)*32, wn = (wid & 1)*64;
    float acc[2][8][4];
    #pragma unroll
    for (int i = 0; i < 2; i++)
        #pragma unroll
        for (int j = 0; j < 8; j++)
            #pragma unroll
            for (int c = 0; c < 4; c++) acc[i][j][c] = 0.f;
    const int am = tid >> 1, ak = (tid & 1)*8, akp = (tid & 1)*4;
    const int kp = tid >> 5, nc = (tid & 31)*4;
    float4 a0 = *(const float4*)&A[(row0+am)*L_ + ak];
    float4 a1 = *(const float4*)&A[(row0+am)*L_ + ak + 4];
    float4 b0 = *(const float4*)&Bm[(2*kp)*H_ + col0 + nc];
    float4 b1 = *(const float4*)&Bm[(2*kp+1)*H_ + col0 + nc];
    for (int kk = 0; kk < L_; kk += 16) {
        __syncthreads();
        As32[akp+0][am] = pk(a0.x, a0.y);
        As32[akp+1][am] = pk(a0.z, a0.w);
        As32[akp+2][am] = pk(a1.x, a1.y);
        As32[akp+3][am] = pk(a1.z, a1.w);
        uint4 bw;
        bw.x = pk(b0.x, b1.x); bw.y = pk(b0.y, b1.y);
        bw.z = pk(b0.z, b1.z); bw.w = pk(b0.w, b1.w);
        *(uint4*)&Bs32[kp][nc] = bw;
        __syncthreads();
        if (kk + 16 < L_) {
            a0 = *(const float4*)&A[(row0+am)*L_ + kk+16 + ak];
            a1 = *(const float4*)&A[(row0+am)*L_ + kk+16 + ak + 4];
            b0 = *(const float4*)&Bm[(kk+16+2*kp)*H_ + col0 + nc];
            b1 = *(const float4*)&Bm[(kk+16+2*kp+1)*H_ + col0 + nc];
        }
        uint32_t af[2][4];
        #pragma unroll
        for (int mt = 0; mt < 2; mt++) {
            int mr = wm + mt*16 + g;
            af[mt][0] = As32[tc][mr];
            af[mt][1] = As32[tc][mr+8];
            af[mt][2] = As32[tc+4][mr];
            af[mt][3] = As32[tc+4][mr+8];
        }
        #pragma unroll
        for (int nt = 0; nt < 8; nt++) {
            int n = wn + nt*8 + g;
            uint32_t bf0 = Bs32[tc][n];
            uint32_t bf1 = Bs32[tc+4][n];
            mma16(acc[0][nt], af[0], bf0, bf1);
            mma16(acc[1][nt], af[1], bf0, bf1);
        }
    }
    #pragma unroll
    for (int mt = 0; mt < 2; mt++) {
        int m = row0 + wm + mt*16 + g;
        #pragma unroll
        for (int nt = 0; nt < 8; nt++) {
            int n = col0 + wn + nt*8 + 2*tc;
            *(float2*)&C[m*H_ + n]     = make_float2(acc[mt][nt][0], acc[mt][nt][1]);
            *(float2*)&C[(m+8)*H_ + n] = make_float2(acc[mt][nt][2], acc[mt][nt][3]);
        }
    }
}

// ---------------- K5a: Hh/Ht = ent_emb @ W*_top (96x1024x768 x2, fp32) -------
__global__ void k_hx(const float* __restrict__ Wh, const float* __restrict__ Wt) {
    const int z = blockIdx.z;
    const float* W = z ? Wt : Wh;
    float* Cout = z ? g_Ht : g_Hh;
    const int row0 = blockIdx.y*32, col0 = blockIdx.x*128;
    __shared__ float As[16][32];
    __shared__ float Bs[16][128];
    float acc[2][8];
    #pragma unroll
    for (int i = 0; i < 2; i++)
        #pragma unroll
        for (int j = 0; j < 8; j++) acc[i][j] = 0.f;
    const int tid = threadIdx.x;
    const int tx = tid & 15, ty = tid >> 4;
    for (int kk = 0; kk < H_; kk += 16) {
        __syncthreads();
        if (tid < 128) {
            int m = tid >> 2, k4 = (tid & 3)*4;
            float4 av = *(const float4*)&g_entemb[(row0+m)*H_ + kk + k4];
            As[k4+0][m] = av.x; As[k4+1][m] = av.y;
            As[k4+2][m] = av.z; As[k4+3][m] = av.w;
        }
        #pragma unroll
        for (int q = 0; q < 2; q++) {
            int idx = q*256 + tid;
            int k = idx >> 5, n4 = (idx & 31)*4;
            *(float4*)&Bs[k][n4] = *(const float4*)&W[(kk+k)*EMB_ + col0 + n4];
        }
        __syncthreads();
        #pragma unroll
        for (int k = 0; k < 16; k++) {
            float a0 = As[k][ty*2], a1 = As[k][ty*2+1];
            float4 b0 = *(const float4*)&Bs[k][tx*8];
            float4 b1 = *(const float4*)&Bs[k][tx*8+4];
            float br[8] = {b0.x,b0.y,b0.z,b0.w,b1.x,b1.y,b1.z,b1.w};
            #pragma unroll
            for (int j = 0; j < 8; j++) {
                acc[0][j] += a0*br[j];
                acc[1][j] += a1*br[j];
            }
        }
    }
    #pragma unroll
    for (int i = 0; i < 2; i++) {
        int m = row0 + ty*2 + i;
        #pragma unroll
        for (int j = 0; j < 8; j += 4) {
            float4 v = make_float4(acc[i][j],acc[i][j+1],acc[i][j+2],acc[i][j+3]);
            *(float4*)&Cout[m*EMB_ + col0 + tx*8 + j] = v;
        }
    }
}

// ---------------- K5b: he/te = tanh(rel @ W*_bot + Hx + b) (fp16 mma) --------
__global__ void k_hete_mma(const float* __restrict__ Wh, const float* __restrict__ Wt,
                           const float* __restrict__ bh, const float* __restrict__ bt,
                           const int* __restrict__ hts) {
    const int col0 = blockIdx.x*128, row0 = blockIdx.y*128;
    const bool head = (col0 < EMB_);
    const float* W = head ? Wh : Wt;
    const int nb = head ? col0 : col0 - EMB_;
    __shared__ uint32_t As32[8][136];
    __shared__ uint32_t Bs32[8][136];
    const int tid = threadIdx.x;
    const int lane = tid & 31, wid = tid >> 5;
    const int g = lane >> 2, tc = lane & 3;
    const int wm = (wid >> 1)*32, wn = (wid & 1)*64;
    float acc[2][8][4];
    #pragma unroll
    for (int i = 0; i < 2; i++)
        #pragma unroll
        for (int j = 0; j < 8; j++)
            #pragma unroll
            for (int c = 0; c < 4; c++) acc[i][j][c] = 0.f;
    const int am = tid >> 1, ak = (tid & 1)*8, akp = (tid & 1)*4;
    const int kp = tid >> 5, nc = (tid & 31)*4;
    float4 a0 = *(const float4*)&g_rel[(row0+am)*H_ + ak];
    float4 a1 = *(const float4*)&g_rel[(row0+am)*H_ + ak + 4];
    float4 b0 = *(const float4*)&W[(H_ + 2*kp)*EMB_ + nb + nc];
    float4 b1 = *(const float4*)&W[(H_ + 2*kp+1)*EMB_ + nb + nc];
    for (int kk = 0; kk < H_; kk += 16) {
        __syncthreads();
        As32[akp+0][am] = pk(a0.x, a0.y);
        As32[akp+1][am] = pk(a0.z, a0.w);
        As32[akp+2][am] = pk(a1.x, a1.y);
        As32[akp+3][am] = pk(a1.z, a1.w);
        uint4 bw;
        bw.x = pk(b0.x, b1.x); bw.y = pk(b0.y, b1.y);
        bw.z = pk(b0.z, b1.z); bw.w = pk(b0.w, b1.w);
        *(uint4*)&Bs32[kp][nc] = bw;
        __syncthreads();
        if (kk + 16 < H_) {
            a0 = *(const float4*)&g_rel[(row0+am)*H_ + kk+16 + ak];
            a1 = *(const float4*)&g_rel[(row0+am)*H_ + kk+16 + ak + 4];
            b0 = *(const float4*)&W[(H_ + kk+16 + 2*kp)*EMB_ + nb + nc];
            b1 = *(const float4*)&W[(H_ + kk+16 + 2*kp+1)*EMB_ + nb + nc];
        }
        uint32_t af[2][4];
        #pragma unroll
        for (int mt = 0; mt < 2; mt++) {
            int mr = wm + mt*16 + g;
            af[mt][0] = As32[tc][mr];
            af[mt][1] = As32[tc][mr+8];
            af[mt][2] = As32[tc+4][mr];
            af[mt][3] = As32[tc+4][mr+8];
        }
        #pragma unroll
        for (int nt = 0; nt < 8; nt++) {
            int n = wn + nt*8 + g;
            uint32_t bf0 = Bs32[tc][n];
            uint32_t bf1 = Bs32[tc+4][n];
            mma16(acc[0][nt], af[0], bf0, bf1);
            mma16(acc[1][nt], af[1], bf0, bf1);
        }
    }
    const float* Hx = head ? g_Hh : g_Ht;
    const float* bias = head ? bh : bt;
    float* outbuf = head ? g_he : g_te;
    #pragma unroll
    for (int mt = 0; mt < 2; mt++) {
        #pragma unroll
        for (int half = 0; half < 2; half++) {
            int m = row0 + wm + mt*16 + g + half*8;
            int b = m >> 9;
            int eidx = hts[m*2 + (head ? 0 : 1)];
            const float* hrow = Hx + (b*E_ + eidx)*EMB_;
            #pragma unroll
            for (int nt = 0; nt < 8; nt++) {
                int n = nb + wn + nt*8 + 2*tc;
                outbuf[m*EMB_ + n]   = tanhf(acc[mt][nt][2*half+0] + hrow[n]   + bias[n]);
                outbuf[m*EMB_ + n+1] = tanhf(acc[mt][nt][2*half+1] + hrow[n+1] + bias[n+1]);
            }
        }
    }
}

// ---------------- K6: Wbc = Wb @ Wc (fp16 mma) -------------------------------
__global__ void k_wbc_mma(const float* __restrict__ Wb, const float* __restrict__ Wc) {
    const int row0 = blockIdx.x*128;
    __shared__ uint32_t As32[8][136];
    __shared__ uint32_t Bs32[8][136];
    const int tid = threadIdx.x;
    const int lane = tid & 31, wid = tid >> 5;
    const int g = lane >> 2, tc = lane & 3;
    const int wm = (wid >> 1)*32, wn = (wid & 1)*64;
    float acc[2][8][4];
    #pragma unroll
    for (int i = 0; i < 2; i++)
        #pragma unroll
        for (int j = 0; j < 8; j++)
            #pragma unroll
            for (int c = 0; c < 4; c++) acc[i][j][c] = 0.f;
    const int am = tid >> 1, ak = (tid & 1)*8, akp = (tid & 1)*4;
    const int kp = tid >> 5, nc = (tid & 31)*4;
    float4 a0 = *(const float4*)&Wb[(row0+am)*EMB_ + ak];
    float4 a1 = *(const float4*)&Wb[(row0+am)*EMB_ + ak + 4];
    float bva[4], bvb[4];
    #pragma unroll
    for (int q = 0; q < 4; q++) {
        int n = nc + q;
        bva[q] = (n < NCLS_) ? Wc[(2*kp)*NCLS_ + n] : 0.f;
        bvb[q] = (n < NCLS_) ? Wc[(2*kp+1)*NCLS_ + n] : 0.f;
    }
    for (int kk = 0; kk < EMB_; kk += 16) {
        __syncthreads();
        As32[akp+0][am] = pk(a0.x, a0.y);
        As32[akp+1][am] = pk(a0.z, a0.w);
        As32[akp+2][am] = pk(a1.x, a1.y);
        As32[akp+3][am] = pk(a1.z, a1.w);
        uint4 bw;
        bw.x = pk(bva[0], bvb[0]); bw.y = pk(bva[1], bvb[1]);
        bw.z = pk(bva[2], bvb[2]); bw.w = pk(bva[3], bvb[3]);
        *(uint4*)&Bs32[kp][nc] = bw;
        __syncthreads();
        if (kk + 16 < EMB_) {
            a0 = *(const float4*)&Wb[(row0+am)*EMB_ + kk+16 + ak];
            a1 = *(const float4*)&Wb[(row0+am)*EMB_ + kk+16 + ak + 4];
            #pragma unroll
            for (int q = 0; q < 4; q++) {
                int n = nc + q;
                bva[q] = (n < NCLS_) ? Wc[(kk+16+2*kp)*NCLS_ + n] : 0.f;
                bvb[q] = (n < NCLS_) ? Wc[(kk+16+2*kp+1)*NCLS_ + n] : 0.f;
            }
        }
        uint32_t af[2][4];
        #pragma unroll
        for (int mt = 0; mt < 2; mt++) {
            int mr = wm + mt*16 + g;
            af[mt][0] = As32[tc][mr];
            af[mt][1] = As32[tc][mr+8];
            af[mt][2] = As32[tc+4][mr];
            af[mt][3] = As32[tc+4][mr+8];
        }
        #pragma unroll
        for (int nt = 0; nt < 8; nt++) {
            int n = wn + nt*8 + g;
            uint32_t bf0 = Bs32[tc][n];
            uint32_t bf1 = Bs32[tc+4][n];
            mma16(acc[0][nt], af[0], bf0, bf1);
            mma16(acc[1][nt], af[1], bf0, bf1);
        }
    }
    #pragma unroll
    for (int mt = 0; mt < 2; mt++) {
        int m = row0 + wm + mt*16 + g;
        #pragma unroll
        for (int nt = 0; nt < 8; nt++) {
            int n = wn + nt*8 + 2*tc;
            *(float2*)&g_Wbc[m*WLD_ + n]     = make_float2(acc[mt][nt][0], acc[mt][nt][1]);
            *(float2*)&g_Wbc[(m+8)*WLD_ + n] = make_float2(acc[mt][nt][2], acc[mt][nt][3]);
        }
    }
}

// ---------------- K6b: pack Wbc float rows -> half2 row-pairs ----------------
__global__ void k_pack() {
    int t = blockIdx.x*256 + threadIdx.x;      // over (WROWS_/2)*32 quads
    int rp = t >> 5, nq = (t & 31)*4;
    float4 e = *(const float4*)&g_Wbc[(2*rp)*WLD_ + nq];
    float4 o = *(const float4*)&g_Wbc[(2*rp+1)*WLD_ + nq];
    uint4 w;
    w.x = pk(e.x, o.x); w.y = pk(e.y, o.y);
    w.z = pk(e.z, o.z); w.w = pk(e.w, o.w);
    *(uint4*)&g_WbcH[rp*WLD_ + nq] = w;
}

// ---------------- K7: bilinear via virtual-A fp16 GEMM, cp.async pipelined ---
// smem (uint32): Bs[2][32][136] | te2[32][136] | he_s(float)[128][68]
#define BIL_U32  (3*32*136 + 128*68)
#define BIL_SMEM (BIL_U32*4)
__global__ void k_bilinear_mma() {
    extern __shared__ uint32_t smu[];
    uint32_t (*BsA)[136] = (uint32_t(*)[136])smu;
    uint32_t (*BsB)[136] = (uint32_t(*)[136])(smu + 32*136);
    uint32_t (*te2)[136] = (uint32_t(*)[136])(smu + 2*32*136);
    float (*he_s)[68]    = (float(*)[68])(smu + 3*32*136);
    const uint32_t sm_u32 = (uint32_t)__cvta_generic_to_shared(smu);
    const int kb = blockIdx.x;
    const int row0 = blockIdx.y*128;
    const int tid = threadIdx.x;
    const int lane = tid & 31, wid = tid >> 5;
    const int g = lane >> 2, tc = lane & 3;
    const int wm = (wid >> 1)*32, wn = (wid & 1)*64;
    // load he (float) and te (packed half2 over j-pairs)
    #pragma unroll
    for (int q = 0; q < 8; q++) {
        int idx = q*256 + tid;
        int m = idx >> 4, c4 = (idx & 15)*4;
        float4 hv = *(const float4*)&g_he[(row0+m)*EMB_ + kb*64 + c4];
        float4 tv = *(const float4*)&g_te[(row0+m)*EMB_ + kb*64 + c4];
        *(float4*)&he_s[m][c4] = hv;
        te2[(c4>>1)+0][m] = pk(tv.x, tv.y);
        te2[(c4>>1)+1][m] = pk(tv.z, tv.w);
    }
    // prologue: stage i=0 into buffer A (16KB packed)
    {
        const uint32_t* src = g_WbcH + (kb*64)*32*WLD_/64;  // = (kb*64+0)*32 rows
        const uint32_t* s0 = g_WbcH + (kb*64)*32*4;         // ((kb*64)*32)*... 
        (void)src; (void)s0;
        const uint32_t* base = g_WbcH + (size_t)(kb*64 + 0)*32*WLD_;
        #pragma unroll
        for (int q = 0; q < 2; q++) {
            int c = q*256 + tid;
            int jp = c >> 4, ncq = (c & 15)*8;   // 32 jp x 128 cols, 8 u32 per thread? no
            (void)jp; (void)ncq;
        }
        // 32 rows x 128 u32 = 4096 u32 = 16 u32/thread = 4 x cp.async16
        #pragma unroll
        for (int q = 0; q < 4; q++) {
            int c = q*256 + tid;
            int jp = c >> 5, ncq = (c & 31)*4;
            cpa16(sm_u32 + (jp*136 + ncq)*4, base + jp*WLD_ + ncq);
        }
        asm volatile("cp.async.commit_group;\n");
    }
    float acc[2][8][4];
    #pragma unroll
    for (int i = 0; i < 2; i++)
        #pragma unroll
        for (int j = 0; j < 8; j++)
            #pragma unroll
            for (int c = 0; c < 4; c++) acc[i][j][c] = 0.f;
    for (int i = 0; i < 64; i++) {
        if (i + 1 < 64) {
            const uint32_t* base = g_WbcH + (size_t)(kb*64 + i + 1)*32*WLD_;
            const uint32_t dstb = sm_u32 + ((i+1)&1)*32*136*4;
            #pragma unroll
            for (int q = 0; q < 4; q++) {
                int c = q*256 + tid;
                int jp = c >> 5, ncq = (c & 31)*4;
                cpa16(dstb + (jp*136 + ncq)*4, base + jp*WLD_ + ncq);
            }
            asm volatile("cp.async.commit_group;\n");
            asm volatile("cp.async.wait_group 1;\n");
        } else {
            asm volatile("cp.async.wait_group 0;\n");
        }
        __syncthreads();
        uint32_t (*Bsb)[136] = (i & 1) ? BsB : BsA;
        uint32_t hb[2][2];
        #pragma unroll
        for (int mt = 0; mt < 2; mt++) {
            int mr = wm + mt*16 + g;
            float h0 = he_s[mr][i], h1 = he_s[mr+8][i];
            hb[mt][0] = pk(h0, h0);
            hb[mt][1] = pk(h1, h1);
        }
        #pragma unroll
        for (int j4 = 0; j4 < 4; j4++) {
            uint32_t af[2][4];
            #pragma unroll
            for (int mt = 0; mt < 2; mt++) {
                int mr = wm + mt*16 + g;
                af[mt][0] = mul2(te2[j4*8+tc][mr],     hb[mt][0]);
                af[mt][1] = mul2(te2[j4*8+tc][mr+8],   hb[mt][1]);
                af[mt][2] = mul2(te2[j4*8+4+tc][mr],   hb[mt][0]);
                af[mt][3] = mul2(te2[j4*8+4+tc][mr+8], hb[mt][1]);
            }
            #pragma unroll
            for (int nt = 0; nt < 8; nt++) {
                int n = wn + nt*8 + g;
                uint32_t bf0 = Bsb[j4*8+tc][n];
                uint32_t bf1 = Bsb[j4*8+4+tc][n];
                mma16(acc[0][nt], af[0], bf0, bf1);
                mma16(acc[1][nt], af[1], bf0, bf1);
            }
        }
        __syncthreads();
    }
    #pragma unroll
    for (int mt = 0; mt < 2; mt++) {
        int m = row0 + wm + mt*16 + g;
        #pragma unroll
        for (int nt = 0; nt < 8; nt++) {
            int n = wn + nt*8 + 2*tc;
            *(float2*)&g_part[(kb*BR_ + m)*WLD_ + n]     = make_float2(acc[mt][nt][0], acc[mt][nt][1]);
            *(float2*)&g_part[(kb*BR_ + m + 8)*WLD_ + n] = make_float2(acc[mt][nt][2], acc[mt][nt][3]);
        }
    }
}

// ---------------- K8: reduce partials + bbc ----------------------------------
__global__ void k_reduce(float* __restrict__ out) {
    int idx = blockIdx.x*256 + threadIdx.x;
    if (idx < BR_*NCLS_) {
        int r = idx / NCLS_, n = idx % NCLS_;
        float a = g_bbc[n];
        #pragma unroll
        for (int k = 0; k < KB_; k++) a += g_part[(k*BR_ + r)*WLD_ + n];
        out[idx] = a;
    }
}

// ---------------- launch -----------------------------------------------------
extern "C" void kernel_launch(void* const* d_in, const int* in_sizes, int n_in,
                              void* d_out, int out_size) {
    const float* seq    = (const float*)d_in[0];
    const float* ent    = (const float*)d_in[1];
    const float* attn   = (const float*)d_in[2];
    const int*   labels = (const int*)  d_in[3];
    const int*   hts    = (const int*)  d_in[4];
    const float* Wh     = (const float*)d_in[5];
    const float* bh     = (const float*)d_in[6];
    const float* Wt     = (const float*)d_in[7];
    const float* bt     = (const float*)d_in[8];
    const float* Wb     = (const float*)d_in[9];
    const float* bb     = (const float*)d_in[10];
    const float* Wc     = (const float*)d_in[11];
    const float* bc     = (const float*)d_in[12];
    float* out = (float*)d_out;

    cudaFuncSetAttribute(k_bilinear_mma,
                         cudaFuncAttributeMaxDynamicSharedMemorySize, BIL_SMEM);

    k_prep<<<1, 128>>>(labels);
    k_bbc<<<1, 128>>>(bb, Wc, bc);
    k_entemb<<<B_*E_, 128>>>(ent);
    k_entattn<<<dim3(B_*E_, NH_), 256>>>(attn);
    k_ht<<<BR_, 256>>>(hts);
    k_rel_mma<<<dim3(H_/128, R_/128, B_), 256>>>(seq);
    k_hx<<<dim3(EMB_/128, 3, 2), 256>>>(Wh, Wt);
    k_hete_mma<<<dim3(12, 16), 256>>>(Wh, Wt, bh, bt, hts);
    k_wbc_mma<<<WROWS_/128, 256>>>(Wb, Wc);
    k_pack<<<(WROWS_/2)*32/256, 256>>>();
    k_bilinear_mma<<<dim3(KB_, 16), 256, BIL_SMEM>>>();
    k_reduce<<<(BR_*NCLS_ + 255)/256, 256>>>(out);
}

// round 12
// speedup vs baseline: 3.2474x; 1.0316x over previous
#include <cuda_runtime.h>
#include <math.h>
#include <stdint.h>

#define B_ 4
#define L_ 1024
#define H_ 1024
#define NH_ 16
#define M_ 64
#define E_ 24
#define R_ 512
#define EMB_ 768
#define NCLS_ 97
#define KB_ 12            // EMB / 64
#define KS_ 24            // K-split slabs for bilinear (2 per kb)
#define BR_ 2048          // B*R
#define WROWS_ 49152      // EMB*64
#define WLD_ 128          // padded N stride for Wbc / partials

// ---------------- scratch (static device globals; no allocation) -------------
__device__ int      g_cnt[B_*E_];
__device__ int      g_mlist[B_*E_*M_];
__device__ float    g_entemb[B_*E_*H_];
__device__ float    g_entattn[B_*E_*NH_*L_];
__device__ float    g_ht[B_*R_*L_];
__device__ float    g_rel[B_*R_*H_];
__device__ float    g_he[BR_*EMB_];
__device__ float    g_te[BR_*EMB_];
__device__ float    g_Hh[B_*E_*EMB_];
__device__ float    g_Ht[B_*E_*EMB_];
__device__ float    g_Wbc[WROWS_*WLD_];
__device__ uint32_t g_WbcH[(WROWS_/2)*WLD_];   // half2-packed over row pairs
__device__ float    g_part[(size_t)KS_*BR_*WLD_];
__device__ float    g_bbc[NCLS_];

// ---------------- fp16 / async helpers ---------------------------------------
__device__ __forceinline__ uint32_t pk(float lo, float hi) {
    uint32_t r;
    asm("cvt.rn.f16x2.f32 %0, %1, %2;" : "=r"(r) : "f"(hi), "f"(lo));
    return r;
}
__device__ __forceinline__ uint32_t mul2(uint32_t a, uint32_t b) {
    uint32_t r;
    asm("mul.rn.f16x2 %0, %1, %2;" : "=r"(r) : "r"(a), "r"(b));
    return r;
}
__device__ __forceinline__ void mma16(float c[4], const uint32_t a[4],
                                      uint32_t b0, uint32_t b1) {
    asm volatile(
        "mma.sync.aligned.m16n8k16.row.col.f32.f16.f16.f32 "
        "{%0,%1,%2,%3}, {%4,%5,%6,%7}, {%8,%9}, {%0,%1,%2,%3};\n"
        : "+f"(c[0]), "+f"(c[1]), "+f"(c[2]), "+f"(c[3])
        : "r"(a[0]), "r"(a[1]), "r"(a[2]), "r"(a[3]), "r"(b0), "r"(b1));
}
__device__ __forceinline__ void cpa16(uint32_t dst, const void* src) {
    asm volatile("cp.async.cg.shared.global [%0], [%1], 16;\n"
                 :: "r"(dst), "l"(src));
}

// ---------------- K0: mention lists per (b,e) --------------------------------
__global__ void k_prep(const int* __restrict__ labels) {
    int t = threadIdx.x;
    if (t < B_*E_) {
        int b = t / E_, e = t % E_;
        int c = 0;
        for (int m = 0; m < M_; m++)
            if (labels[b*M_ + m] == e) g_mlist[t*M_ + c++] = m;
        g_cnt[t] = c;
    }
}

// ---------------- bbc = bb @ Wc + bc ----------------------------------------
__global__ void k_bbc(const float* __restrict__ bb, const float* __restrict__ Wc,
                      const float* __restrict__ bc) {
    int n = threadIdx.x;
    if (n < NCLS_) {
        float a = bc[n];
        for (int d = 0; d < EMB_; d++) a += bb[d] * Wc[d*NCLS_ + n];
        g_bbc[n] = a;
    }
}

// ---------------- K1: entity logsumexp pooling -------------------------------
__global__ void k_entemb(const float* __restrict__ ent) {
    int be = blockIdx.x;
    int b = be / E_;
    __shared__ int lst[M_];
    __shared__ int scnt;
    if (threadIdx.x == 0) scnt = g_cnt[be];
    __syncthreads();
    int cnt = scnt;
    if (threadIdx.x < cnt) lst[threadIdx.x] = g_mlist[be*M_ + threadIdx.x];
    __syncthreads();
    for (int h = threadIdx.x; h < H_; h += blockDim.x) {
        float o = 0.f;
        if (cnt > 0) {
            float mx = -3.4e38f;
            for (int c = 0; c < cnt; c++)
                mx = fmaxf(mx, ent[(b*M_ + lst[c])*H_ + h]);
            float s = 0.f;
            for (int c = 0; c < cnt; c++)
                s += expf(ent[(b*M_ + lst[c])*H_ + h] - mx);
            o = mx + logf(s);
        }
        g_entemb[be*H_ + h] = o;
    }
}

// ---------------- K2: entity->seq attention (mean over mentions) -------------
__global__ void k_entattn(const float* __restrict__ attn) {
    int be = blockIdx.x, nh = blockIdx.y;
    int b = be / E_;
    __shared__ int lst[M_];
    __shared__ int scnt;
    if (threadIdx.x == 0) scnt = g_cnt[be];
    __syncthreads();
    int cnt = scnt;
    if (threadIdx.x < cnt) lst[threadIdx.x] = g_mlist[be*M_ + threadIdx.x];
    __syncthreads();
    float inv = 1.f / (float)(cnt > 1 ? cnt : 1);
    const float* base = attn + (b*NH_ + nh)*M_*L_;
    float* outp = g_entattn + (be*NH_ + nh)*L_;
    for (int l = threadIdx.x; l < L_; l += blockDim.x) {
        float a = 0.f;
        for (int c = 0; c < cnt; c++) a += base[lst[c]*L_ + l];
        outp[l] = a * inv;
    }
}

// ---------------- K3: pair attention product + normalize ---------------------
__global__ void k_ht(const int* __restrict__ hts) {
    int br = blockIdx.x;
    int b = br >> 9;
    int h = hts[br*2 + 0], t = hts[br*2 + 1];
    const float* ph = g_entattn + (b*E_ + h)*NH_*L_;
    const float* pt = g_entattn + (b*E_ + t)*NH_*L_;
    float v[4];
    float lsum = 0.f;
    #pragma unroll
    for (int q = 0; q < 4; q++) {
        int l = threadIdx.x + q*256;
        float s = 0.f;
        #pragma unroll
        for (int nh = 0; nh < NH_; nh++)
            s += ph[nh*L_ + l] * pt[nh*L_ + l];
        v[q] = s * (1.f/NH_);
        lsum += v[q];
    }
    __shared__ float red[256];
    red[threadIdx.x] = lsum;
    __syncthreads();
    for (int s = 128; s > 0; s >>= 1) {
        if (threadIdx.x < s) red[threadIdx.x] += red[threadIdx.x + s];
        __syncthreads();
    }
    float inv = 1.f / (red[0] + 1e-5f);
    #pragma unroll
    for (int q = 0; q < 4; q++) {
        int l = threadIdx.x + q*256;
        g_ht[br*L_ + l] = v[q] * inv;
    }
}

// ---------------- K4: rel = ht @ seq (fp16 mma, reg-prefetch pipelined) ------
__global__ void k_rel_mma(const float* __restrict__ seq) {
    const int b = blockIdx.z;
    const float* A = g_ht + b*R_*L_;
    const float* Bm = seq + b*L_*H_;
    float* C = g_rel + b*R_*H_;
    const int row0 = blockIdx.y*128, col0 = blockIdx.x*128;
    __shared__ uint32_t As32[8][136];
    __shared__ uint32_t Bs32[8][136];
    const int tid = threadIdx.x;
    const int lane = tid & 31, wid = tid >> 5;
    const int g = lane >> 2, tc = lane & 3;
    const int wm = (wid >> 1)*32, wn = (wid & 1)*64;
    float acc[2][8][4];
    #pragma unroll
    for (int i = 0; i < 2; i++)
        #pragma unroll
        for (int j = 0; j < 8; j++)
            #pragma unroll
            for (int c = 0; c < 4; c++) acc[i][j][c] = 0.f;
    const int am = tid >> 1, ak = (tid & 1)*8, akp = (tid & 1)*4;
    const int kp = tid >> 5, nc = (tid & 31)*4;
    float4 a0 = *(const float4*)&A[(row0+am)*L_ + ak];
    float4 a1 = *(const float4*)&A[(row0+am)*L_ + ak + 4];
    float4 b0 = *(const float4*)&Bm[(2*kp)*H_ + col0 + nc];
    float4 b1 = *(const float4*)&Bm[(2*kp+1)*H_ + col0 + nc];
    for (int kk = 0; kk < L_; kk += 16) {
        __syncthreads();
        As32[akp+0][am] = pk(a0.x, a0.y);
        As32[akp+1][am] = pk(a0.z, a0.w);
        As32[akp+2][am] = pk(a1.x, a1.y);
        As32[akp+3][am] = pk(a1.z, a1.w);
        uint4 bw;
        bw.x = pk(b0.x, b1.x); bw.y = pk(b0.y, b1.y);
        bw.z = pk(b0.z, b1.z); bw.w = pk(b0.w, b1.w);
        *(uint4*)&Bs32[kp][nc] = bw;
        __syncthreads();
        if (kk + 16 < L_) {
            a0 = *(const float4*)&A[(row0+am)*L_ + kk+16 + ak];
            a1 = *(const float4*)&A[(row0+am)*L_ + kk+16 + ak + 4];
            b0 = *(const float4*)&Bm[(kk+16+2*kp)*H_ + col0 + nc];
            b1 = *(const float4*)&Bm[(kk+16+2*kp+1)*H_ + col0 + nc];
        }
        uint32_t af[2][4];
        #pragma unroll
        for (int mt = 0; mt < 2; mt++) {
            int mr = wm + mt*16 + g;
            af[mt][0] = As32[tc][mr];
            af[mt][1] = As32[tc][mr+8];
            af[mt][2] = As32[tc+4][mr];
            af[mt][3] = As32[tc+4][mr+8];
        }
        #pragma unroll
        for (int nt = 0; nt < 8; nt++) {
            int n = wn + nt*8 + g;
            uint32_t bf0 = Bs32[tc][n];
            uint32_t bf1 = Bs32[tc+4][n];
            mma16(acc[0][nt], af[0], bf0, bf1);
            mma16(acc[1][nt], af[1], bf0, bf1);
        }
    }
    #pragma unroll
    for (int mt = 0; mt < 2; mt++) {
        int m = row0 + wm + mt*16 + g;
        #pragma unroll
        for (int nt = 0; nt < 8; nt++) {
            int n = col0 + wn + nt*8 + 2*tc;
            *(float2*)&C[m*H_ + n]     = make_float2(acc[mt][nt][0], acc[mt][nt][1]);
            *(float2*)&C[(m+8)*H_ + n] = make_float2(acc[mt][nt][2], acc[mt][nt][3]);
        }
    }
}

// ---------------- K5a: Hh/Ht = ent_emb @ W*_top (96x1024x768 x2, fp32) -------
__global__ void k_hx(const float* __restrict__ Wh, const float* __restrict__ Wt) {
    const int z = blockIdx.z;
    const float* W = z ? Wt : Wh;
    float* Cout = z ? g_Ht : g_Hh;
    const int row0 = blockIdx.y*32, col0 = blockIdx.x*128;
    __shared__ float As[16][32];
    __shared__ float Bs[16][128];
    float acc[2][8];
    #pragma unroll
    for (int i = 0; i < 2; i++)
        #pragma unroll
        for (int j = 0; j < 8; j++) acc[i][j] = 0.f;
    const int tid = threadIdx.x;
    const int tx = tid & 15, ty = tid >> 4;
    for (int kk = 0; kk < H_; kk += 16) {
        __syncthreads();
        if (tid < 128) {
            int m = tid >> 2, k4 = (tid & 3)*4;
            float4 av = *(const float4*)&g_entemb[(row0+m)*H_ + kk + k4];
            As[k4+0][m] = av.x; As[k4+1][m] = av.y;
            As[k4+2][m] = av.z; As[k4+3][m] = av.w;
        }
        #pragma unroll
        for (int q = 0; q < 2; q++) {
            int idx = q*256 + tid;
            int k = idx >> 5, n4 = (idx & 31)*4;
            *(float4*)&Bs[k][n4] = *(const float4*)&W[(kk+k)*EMB_ + col0 + n4];
        }
        __syncthreads();
        #pragma unroll
        for (int k = 0; k < 16; k++) {
            float a0 = As[k][ty*2], a1 = As[k][ty*2+1];
            float4 b0 = *(const float4*)&Bs[k][tx*8];
            float4 b1 = *(const float4*)&Bs[k][tx*8+4];
            float br[8] = {b0.x,b0.y,b0.z,b0.w,b1.x,b1.y,b1.z,b1.w};
            #pragma unroll
            for (int j = 0; j < 8; j++) {
                acc[0][j] += a0*br[j];
                acc[1][j] += a1*br[j];
            }
        }
    }
    #pragma unroll
    for (int i = 0; i < 2; i++) {
        int m = row0 + ty*2 + i;
        #pragma unroll
        for (int j = 0; j < 8; j += 4) {
            float4 v = make_float4(acc[i][j],acc[i][j+1],acc[i][j+2],acc[i][j+3]);
            *(float4*)&Cout[m*EMB_ + col0 + tx*8 + j] = v;
        }
    }
}

// ---------------- K5b: he/te = tanh(rel @ W*_bot + Hx + b) (fp16 mma) --------
__global__ void k_hete_mma(const float* __restrict__ Wh, const float* __restrict__ Wt,
                           const float* __restrict__ bh, const float* __restrict__ bt,
                           const int* __restrict__ hts) {
    const int col0 = blockIdx.x*128, row0 = blockIdx.y*128;
    const bool head = (col0 < EMB_);
    const float* W = head ? Wh : Wt;
    const int nb = head ? col0 : col0 - EMB_;
    __shared__ uint32_t As32[8][136];
    __shared__ uint32_t Bs32[8][136];
    const int tid = threadIdx.x;
    const int lane = tid & 31, wid = tid >> 5;
    const int g = lane >> 2, tc = lane & 3;
    const int wm = (wid >> 1)*32, wn = (wid & 1)*64;
    float acc[2][8][4];
    #pragma unroll
    for (int i = 0; i < 2; i++)
        #pragma unroll
        for (int j = 0; j < 8; j++)
            #pragma unroll
            for (int c = 0; c < 4; c++) acc[i][j][c] = 0.f;
    const int am = tid >> 1, ak = (tid & 1)*8, akp = (tid & 1)*4;
    const int kp = tid >> 5, nc = (tid & 31)*4;
    float4 a0 = *(const float4*)&g_rel[(row0+am)*H_ + ak];
    float4 a1 = *(const float4*)&g_rel[(row0+am)*H_ + ak + 4];
    float4 b0 = *(const float4*)&W[(H_ + 2*kp)*EMB_ + nb + nc];
    float4 b1 = *(const float4*)&W[(H_ + 2*kp+1)*EMB_ + nb + nc];
    for (int kk = 0; kk < H_; kk += 16) {
        __syncthreads();
        As32[akp+0][am] = pk(a0.x, a0.y);
        As32[akp+1][am] = pk(a0.z, a0.w);
        As32[akp+2][am] = pk(a1.x, a1.y);
        As32[akp+3][am] = pk(a1.z, a1.w);
        uint4 bw;
        bw.x = pk(b0.x, b1.x); bw.y = pk(b0.y, b1.y);
        bw.z = pk(b0.z, b1.z); bw.w = pk(b0.w, b1.w);
        *(uint4*)&Bs32[kp][nc] = bw;
        __syncthreads();
        if (kk + 16 < H_) {
            a0 = *(const float4*)&g_rel[(row0+am)*H_ + kk+16 + ak];
            a1 = *(const float4*)&g_rel[(row0+am)*H_ + kk+16 + ak + 4];
            b0 = *(const float4*)&W[(H_ + kk+16 + 2*kp)*EMB_ + nb + nc];
            b1 = *(const float4*)&W[(H_ + kk+16 + 2*kp+1)*EMB_ + nb + nc];
        }
        uint32_t af[2][4];
        #pragma unroll
        for (int mt = 0; mt < 2; mt++) {
            int mr = wm + mt*16 + g;
            af[mt][0] = As32[tc][mr];
            af[mt][1] = As32[tc][mr+8];
            af[mt][2] = As32[tc+4][mr];
            af[mt][3] = As32[tc+4][mr+8];
        }
        #pragma unroll
        for (int nt = 0; nt < 8; nt++) {
            int n = wn + nt*8 + g;
            uint32_t bf0 = Bs32[tc][n];
            uint32_t bf1 = Bs32[tc+4][n];
            mma16(acc[0][nt], af[0], bf0, bf1);
            mma16(acc[1][nt], af[1], bf0, bf1);
        }
    }
    const float* Hx = head ? g_Hh : g_Ht;
    const float* bias = head ? bh : bt;
    float* outbuf = head ? g_he : g_te;
    #pragma unroll
    for (int mt = 0; mt < 2; mt++) {
        #pragma unroll
        for (int half = 0; half < 2; half++) {
            int m = row0 + wm + mt*16 + g + half*8;
            int b = m >> 9;
            int eidx = hts[m*2 + (head ? 0 : 1)];
            const float* hrow = Hx + (b*E_ + eidx)*EMB_;
            #pragma unroll
            for (int nt = 0; nt < 8; nt++) {
                int n = nb + wn + nt*8 + 2*tc;
                outbuf[m*EMB_ + n]   = tanhf(acc[mt][nt][2*half+0] + hrow[n]   + bias[n]);
                outbuf[m*EMB_ + n+1] = tanhf(acc[mt][nt][2*half+1] + hrow[n+1] + bias[n+1]);
            }
        }
    }
}

// ---------------- K6: Wbc = Wb @ Wc (fp16 mma, only 104 N cols computed) -----
__global__ void k_wbc_mma(const float* __restrict__ Wb, const float* __restrict__ Wc) {
    const int row0 = blockIdx.x*128;
    __shared__ uint32_t As32[8][136];
    __shared__ uint32_t Bs32[8][136];
    const int tid = threadIdx.x;
    const int lane = tid & 31, wid = tid >> 5;
    const int g = lane >> 2, tc = lane & 3;
    const int wm = (wid >> 1)*32, wn = (wid & 1)*64;
    const int ntmax = (wid & 1) ? 5 : 8;   // cols >= 104 never consumed
    float acc[2][8][4];
    #pragma unroll
    for (int i = 0; i < 2; i++)
        #pragma unroll
        for (int j = 0; j < 8; j++)
            #pragma unroll
            for (int c = 0; c < 4; c++) acc[i][j][c] = 0.f;
    const int am = tid >> 1, ak = (tid & 1)*8, akp = (tid & 1)*4;
    const int kp = tid >> 5, nc = (tid & 31)*4;
    float4 a0 = *(const float4*)&Wb[(row0+am)*EMB_ + ak];
    float4 a1 = *(const float4*)&Wb[(row0+am)*EMB_ + ak + 4];
    float bva[4], bvb[4];
    #pragma unroll
    for (int q = 0; q < 4; q++) {
        int n = nc + q;
        bva[q] = (n < NCLS_) ? Wc[(2*kp)*NCLS_ + n] : 0.f;
        bvb[q] = (n < NCLS_) ? Wc[(2*kp+1)*NCLS_ + n] : 0.f;
    }
    for (int kk = 0; kk < EMB_; kk += 16) {
        __syncthreads();
        As32[akp+0][am] = pk(a0.x, a0.y);
        As32[akp+1][am] = pk(a0.z, a0.w);
        As32[akp+2][am] = pk(a1.x, a1.y);
        As32[akp+3][am] = pk(a1.z, a1.w);
        uint4 bw;
        bw.x = pk(bva[0], bvb[0]); bw.y = pk(bva[1], bvb[1]);
        bw.z = pk(bva[2], bvb[2]); bw.w = pk(bva[3], bvb[3]);
        *(uint4*)&Bs32[kp][nc] = bw;
        __syncthreads();
        if (kk + 16 < EMB_) {
            a0 = *(const float4*)&Wb[(row0+am)*EMB_ + kk+16 + ak];
            a1 = *(const float4*)&Wb[(row0+am)*EMB_ + kk+16 + ak + 4];
            #pragma unroll
            for (int q = 0; q < 4; q++) {
                int n = nc + q;
                bva[q] = (n < NCLS_) ? Wc[(kk+16+2*kp)*NCLS_ + n] : 0.f;
                bvb[q] = (n < NCLS_) ? Wc[(kk+16+2*kp+1)*NCLS_ + n] : 0.f;
            }
        }
        uint32_t af[2][4];
        #pragma unroll
        for (int mt = 0; mt < 2; mt++) {
            int mr = wm + mt*16 + g;
            af[mt][0] = As32[tc][mr];
            af[mt][1] = As32[tc][mr+8];
            af[mt][2] = As32[tc+4][mr];
            af[mt][3] = As32[tc+4][mr+8];
        }
        #pragma unroll
        for (int nt = 0; nt < 8; nt++) {
            if (nt < ntmax) {
                int n = wn + nt*8 + g;
                uint32_t bf0 = Bs32[tc][n];
                uint32_t bf1 = Bs32[tc+4][n];
                mma16(acc[0][nt], af[0], bf0, bf1);
                mma16(acc[1][nt], af[1], bf0, bf1);
            }
        }
    }
    #pragma unroll
    for (int mt = 0; mt < 2; mt++) {
        int m = row0 + wm + mt*16 + g;
        #pragma unroll
        for (int nt = 0; nt < 8; nt++) {
            if (nt < ntmax) {
                int n = wn + nt*8 + 2*tc;
                *(float2*)&g_Wbc[m*WLD_ + n]     = make_float2(acc[mt][nt][0], acc[mt][nt][1]);
                *(float2*)&g_Wbc[(m+8)*WLD_ + n] = make_float2(acc[mt][nt][2], acc[mt][nt][3]);
            }
        }
    }
}

// ---------------- K6b: pack Wbc float rows -> half2 row-pairs ----------------
// cols 104..127 of g_Wbc are zero-init (never written) -> packed zeros, unused.
__global__ void k_pack() {
    int t = blockIdx.x*256 + threadIdx.x;      // over (WROWS_/2)*32 quads
    int rp = t >> 5, nq = (t & 31)*4;
    float4 e = *(const float4*)&g_Wbc[(2*rp)*WLD_ + nq];
    float4 o = *(const float4*)&g_Wbc[(2*rp+1)*WLD_ + nq];
    uint4 w;
    w.x = pk(e.x, o.x); w.y = pk(e.y, o.y);
    w.z = pk(e.z, o.z); w.w = pk(e.w, o.w);
    *(uint4*)&g_WbcH[rp*WLD_ + nq] = w;
}

// ---------------- K7: bilinear via virtual-A fp16 GEMM, cp.async pipelined ---
// grid (KS_=24, 16): blockIdx.x = kb*2 + ih; each CTA covers i in [ih*32, ih*32+32)
// smem (uint32): Bs[2][32][136] | te2[32][136] | he_s(float)[128][68]
#define BIL_U32  (3*32*136 + 128*68)
#define BIL_SMEM (BIL_U32*4)
__global__ void k_bilinear_mma() {
    extern __shared__ uint32_t smu[];
    uint32_t (*BsA)[136] = (uint32_t(*)[136])smu;
    uint32_t (*BsB)[136] = (uint32_t(*)[136])(smu + 32*136);
    uint32_t (*te2)[136] = (uint32_t(*)[136])(smu + 2*32*136);
    float (*he_s)[68]    = (float(*)[68])(smu + 3*32*136);
    const uint32_t sm_u32 = (uint32_t)__cvta_generic_to_shared(smu);
    const int bx = blockIdx.x;
    const int kb = bx >> 1, ih = bx & 1;
    const int i0 = ih*32;
    const int row0 = blockIdx.y*128;
    const int tid = threadIdx.x;
    const int lane = tid & 31, wid = tid >> 5;
    const int g = lane >> 2, tc = lane & 3;
    const int wm = (wid >> 1)*32, wn = (wid & 1)*64;
    const int ntmax = (wid & 1) ? 5 : 8;   // cols >= 104 never consumed
    // load he (float) and te (packed half2 over j-pairs)
    #pragma unroll
    for (int q = 0; q < 8; q++) {
        int idx = q*256 + tid;
        int m = idx >> 4, c4 = (idx & 15)*4;
        float4 hv = *(const float4*)&g_he[(row0+m)*EMB_ + kb*64 + c4];
        float4 tv = *(const float4*)&g_te[(row0+m)*EMB_ + kb*64 + c4];
        *(float4*)&he_s[m][c4] = hv;
        te2[(c4>>1)+0][m] = pk(tv.x, tv.y);
        te2[(c4>>1)+1][m] = pk(tv.z, tv.w);
    }
    // prologue: stage first i into buffer A (16KB packed)
    {
        const uint32_t* base = g_WbcH + (size_t)(kb*64 + i0)*32*WLD_;
        #pragma unroll
        for (int q = 0; q < 4; q++) {
            int c = q*256 + tid;
            int jp = c >> 5, ncq = (c & 31)*4;
            cpa16(sm_u32 + (jp*136 + ncq)*4, base + jp*WLD_ + ncq);
        }
        asm volatile("cp.async.commit_group;\n");
    }
    float acc[2][8][4];
    #pragma unroll
    for (int i = 0; i < 2; i++)
        #pragma unroll
        for (int j = 0; j < 8; j++)
            #pragma unroll
            for (int c = 0; c < 4; c++) acc[i][j][c] = 0.f;
    for (int i = 0; i < 32; i++) {
        if (i + 1 < 32) {
            const uint32_t* base = g_WbcH + (size_t)(kb*64 + i0 + i + 1)*32*WLD_;
            const uint32_t dstb = sm_u32 + ((i+1)&1)*32*136*4;
            #pragma unroll
            for (int q = 0; q < 4; q++) {
                int c = q*256 + tid;
                int jp = c >> 5, ncq = (c & 31)*4;
                cpa16(dstb + (jp*136 + ncq)*4, base + jp*WLD_ + ncq);
            }
            asm volatile("cp.async.commit_group;\n");
            asm volatile("cp.async.wait_group 1;\n");
        } else {
            asm volatile("cp.async.wait_group 0;\n");
        }
        __syncthreads();
        uint32_t (*Bsb)[136] = (i & 1) ? BsB : BsA;
        uint32_t hb[2][2];
        #pragma unroll
        for (int mt = 0; mt < 2; mt++) {
            int mr = wm + mt*16 + g;
            float h0 = he_s[mr][i0 + i], h1 = he_s[mr+8][i0 + i];
            hb[mt][0] = pk(h0, h0);
            hb[mt][1] = pk(h1, h1);
        }
        #pragma unroll
        for (int j4 = 0; j4 < 4; j4++) {
            uint32_t af[2][4];
            #pragma unroll
            for (int mt = 0; mt < 2; mt++) {
                int mr = wm + mt*16 + g;
                af[mt][0] = mul2(te2[j4*8+tc][mr],     hb[mt][0]);
                af[mt][1] = mul2(te2[j4*8+tc][mr+8],   hb[mt][1]);
                af[mt][2] = mul2(te2[j4*8+4+tc][mr],   hb[mt][0]);
                af[mt][3] = mul2(te2[j4*8+4+tc][mr+8], hb[mt][1]);
            }
            #pragma unroll
            for (int nt = 0; nt < 8; nt++) {
                if (nt < ntmax) {
                    int n = wn + nt*8 + g;
                    uint32_t bf0 = Bsb[j4*8+tc][n];
                    uint32_t bf1 = Bsb[j4*8+4+tc][n];
                    mma16(acc[0][nt], af[0], bf0, bf1);
                    mma16(acc[1][nt], af[1], bf0, bf1);
                }
            }
        }
        __syncthreads();
    }
    #pragma unroll
    for (int mt = 0; mt < 2; mt++) {
        int m = row0 + wm + mt*16 + g;
        #pragma unroll
        for (int nt = 0; nt < 8; nt++) {
            if (nt < ntmax) {
                int n = wn + nt*8 + 2*tc;
                *(float2*)&g_part[((size_t)bx*BR_ + m)*WLD_ + n]     = make_float2(acc[mt][nt][0], acc[mt][nt][1]);
                *(float2*)&g_part[((size_t)bx*BR_ + m + 8)*WLD_ + n] = make_float2(acc[mt][nt][2], acc[mt][nt][3]);
            }
        }
    }
}

// ---------------- K8: reduce partials + bbc ----------------------------------
__global__ void k_reduce(float* __restrict__ out) {
    int idx = blockIdx.x*256 + threadIdx.x;
    if (idx < BR_*NCLS_) {
        int r = idx / NCLS_, n = idx % NCLS_;
        float a = g_bbc[n];
        #pragma unroll
        for (int k = 0; k < KS_; k++) a += g_part[((size_t)k*BR_ + r)*WLD_ + n];
        out[idx] = a;
    }
}

// ---------------- launch -----------------------------------------------------
extern "C" void kernel_launch(void* const* d_in, const int* in_sizes, int n_in,
                              void* d_out, int out_size) {
    const float* seq    = (const float*)d_in[0];
    const float* ent    = (const float*)d_in[1];
    const float* attn   = (const float*)d_in[2];
    const int*   labels = (const int*)  d_in[3];
    const int*   hts    = (const int*)  d_in[4];
    const float* Wh     = (const float*)d_in[5];
    const float* bh     = (const float*)d_in[6];
    const float* Wt     = (const float*)d_in[7];
    const float* bt     = (const float*)d_in[8];
    const float* Wb     = (const float*)d_in[9];
    const float* bb     = (const float*)d_in[10];
    const float* Wc     = (const float*)d_in[11];
    const float* bc     = (const float*)d_in[12];
    float* out = (float*)d_out;

    cudaFuncSetAttribute(k_bilinear_mma,
                         cudaFuncAttributeMaxDynamicSharedMemorySize, BIL_SMEM);

    k_prep<<<1, 128>>>(labels);
    k_bbc<<<1, 128>>>(bb, Wc, bc);
    k_entemb<<<B_*E_, 128>>>(ent);
    k_entattn<<<dim3(B_*E_, NH_), 256>>>(attn);
    k_ht<<<BR_, 256>>>(hts);
    k_rel_mma<<<dim3(H_/128, R_/128, B_), 256>>>(seq);
    k_hx<<<dim3(EMB_/128, 3, 2), 256>>>(Wh, Wt);
    k_hete_mma<<<dim3(12, 16), 256>>>(Wh, Wt, bh, bt, hts);
    k_wbc_mma<<<WROWS_/128, 256>>>(Wb, Wc);
    k_pack<<<(WROWS_/2)*32/256, 256>>>();
    k_bilinear_mma<<<dim3(KS_, 16), 256, BIL_SMEM>>>();
    k_reduce<<<(BR_*NCLS_ + 255)/256, 256>>>(out);
}